// round 1
// baseline (speedup 1.0000x reference)
#include <cuda_runtime.h>
#include <math.h>

#define BB 4
#define TT 4096
#define DD 1024
#define HEADS 16
#define HDIM 64
#define FF 4096
#define KK 512
#define BT (BB*TT)      // 16384
#define BKr (BB*KK)     // 2048 selected rows total

// ---------------- scratch (static device globals; no cudaMalloc allowed) ----
__device__ float g_logits[BT];
__device__ int   g_idx[BKr];
__device__ float g_gates[BKr];
__device__ float g_xsel[BKr*DD];
__device__ float g_h[BKr*DD];
__device__ float g_q[BKr*DD];
__device__ float g_k[BKr*DD];
__device__ float g_v[BKr*DD];
__device__ float g_o[BKr*DD];
__device__ float g_x1[BKr*DD];
__device__ float g_h2[BKr*DD];
__device__ float g_gateb[BKr*FF];
__device__ float g_upb[BKr*FF];
__device__ float g_bo[BKr*DD];

// ---------------- block reduction helpers --------------------------------
__device__ __forceinline__ float blk_sum(float v, float* red) {
    int lane = threadIdx.x & 31, w = threadIdx.x >> 5;
    #pragma unroll
    for (int o = 16; o; o >>= 1) v += __shfl_down_sync(0xffffffffu, v, o);
    if (lane == 0) red[w] = v;
    __syncthreads();
    int nw = (blockDim.x + 31) >> 5;
    if (threadIdx.x < 32) {
        float t = (threadIdx.x < nw) ? red[threadIdx.x] : 0.f;
        #pragma unroll
        for (int o = 16; o; o >>= 1) t += __shfl_down_sync(0xffffffffu, t, o);
        if (threadIdx.x == 0) red[0] = t;
    }
    __syncthreads();
    float r = red[0];
    __syncthreads();
    return r;
}

__device__ __forceinline__ float blk_max(float v, float* red) {
    int lane = threadIdx.x & 31, w = threadIdx.x >> 5;
    #pragma unroll
    for (int o = 16; o; o >>= 1) v = fmaxf(v, __shfl_down_sync(0xffffffffu, v, o));
    if (lane == 0) red[w] = v;
    __syncthreads();
    int nw = (blockDim.x + 31) >> 5;
    if (threadIdx.x < 32) {
        float t = (threadIdx.x < nw) ? red[threadIdx.x] : -1e30f;
        #pragma unroll
        for (int o = 16; o; o >>= 1) t = fmaxf(t, __shfl_down_sync(0xffffffffu, t, o));
        if (threadIdx.x == 0) red[0] = t;
    }
    __syncthreads();
    float r = red[0];
    __syncthreads();
    return r;
}

// ---------------- router logits: one warp per token ----------------------
__global__ void router_kernel(const float* __restrict__ hs, const float* __restrict__ wr) {
    int warp = (blockIdx.x * blockDim.x + threadIdx.x) >> 5;
    int lane = threadIdx.x & 31;
    if (warp >= BT) return;
    const float4* row = (const float4*)(hs + (size_t)warp * DD);
    const float4* w   = (const float4*)wr;
    float s = 0.f;
    #pragma unroll
    for (int it = 0; it < 8; it++) {
        float4 a = row[lane + 32 * it];
        float4 b = w[lane + 32 * it];
        s += a.x*b.x + a.y*b.y + a.z*b.z + a.w*b.w;
    }
    #pragma unroll
    for (int o = 16; o; o >>= 1) s += __shfl_down_sync(0xffffffffu, s, o);
    if (lane == 0) g_logits[warp] = s;
}

// ---------------- top-k via full bitonic sort (block per batch) ----------
__global__ void topk_kernel() {
    __shared__ float vals[TT];
    __shared__ int   inds[TT];
    int b = blockIdx.x;
    int tid = threadIdx.x;   // 1024
    for (int i = tid; i < TT; i += 1024) { vals[i] = g_logits[b*TT + i]; inds[i] = i; }
    __syncthreads();
    // full descending sort by (value desc, index asc for ties)
    for (int k = 2; k <= TT; k <<= 1) {
        for (int j = k >> 1; j > 0; j >>= 1) {
            for (int i = tid; i < TT; i += 1024) {
                int ixj = i ^ j;
                if (ixj > i) {
                    float va = vals[i], vb = vals[ixj];
                    int ia = inds[i], ib = inds[ixj];
                    bool a_first = (va > vb) || (va == vb && ia < ib);
                    bool desc = ((i & k) == 0);
                    if (desc ? !a_first : a_first) {
                        vals[i] = vb; vals[ixj] = va;
                        inds[i] = ib; inds[ixj] = ia;
                    }
                }
            }
            __syncthreads();
        }
    }
    // sort first KK indices ascending
    for (int k = 2; k <= KK; k <<= 1) {
        for (int j = k >> 1; j > 0; j >>= 1) {
            if (tid < KK) {
                int i = tid, ixj = i ^ j;
                if (ixj > i) {
                    int a = inds[i], c = inds[ixj];
                    bool asc = ((i & k) == 0);
                    if (asc ? (a > c) : (a < c)) { inds[i] = c; inds[ixj] = a; }
                }
            }
            __syncthreads();
        }
    }
    if (tid < KK) {
        int id = inds[tid];
        g_idx[b*KK + tid] = id;
        float l = g_logits[b*TT + id];
        g_gates[b*KK + tid] = 1.f / (1.f + expf(-l));
    }
}

// ---------------- aux loss: single block, deterministic ------------------
__global__ void aux_kernel(float* __restrict__ out, int aux_off) {
    __shared__ float red[32];
    float s = 0.f;
    for (int i = threadIdx.x; i < BT; i += blockDim.x) {
        float l = g_logits[i];
        s += fmaxf(l, 0.f) + log1pf(expf(-fabsf(l)));
    }
    for (int i = threadIdx.x; i < BKr; i += blockDim.x) {
        int b = i >> 9;
        s -= g_logits[b*TT + g_idx[i]];
    }
    float tot = blk_sum(s, red);
    if (threadIdx.x == 0) out[aux_off] = tot * (0.01f / (float)BT);
}

// ---------------- gather + rmsnorm1 (block per selected row) -------------
__global__ void gather_rms1(const float* __restrict__ hs, const float* __restrict__ ln1) {
    __shared__ float red[32];
    int bj = blockIdx.x;
    int b = bj >> 9;
    int row = g_idx[bj];
    const float4* src = (const float4*)(hs + ((size_t)(b*TT + row)) * DD);
    float4 x = src[threadIdx.x];
    float ss = x.x*x.x + x.y*x.y + x.z*x.z + x.w*x.w;
    float tot = blk_sum(ss, red);
    float r = rsqrtf(tot / (float)DD + 1e-6f);
    ((float4*)g_xsel)[bj*256 + threadIdx.x] = x;
    float4 w = ((const float4*)ln1)[threadIdx.x];
    float4 hv = make_float4(x.x*r*w.x, x.y*r*w.y, x.z*r*w.z, x.w*r*w.w);
    ((float4*)g_h)[bj*256 + threadIdx.x] = hv;
}

// ---------------- rmsnorm2: g_x1 -> g_h2 ---------------------------------
__global__ void rms2_kernel(const float* __restrict__ ln2) {
    __shared__ float red[32];
    int bj = blockIdx.x;
    float4 x = ((const float4*)g_x1)[bj*256 + threadIdx.x];
    float ss = x.x*x.x + x.y*x.y + x.z*x.z + x.w*x.w;
    float tot = blk_sum(ss, red);
    float r = rsqrtf(tot / (float)DD + 1e-6f);
    float4 w = ((const float4*)ln2)[threadIdx.x];
    float4 hv = make_float4(x.x*r*w.x, x.y*r*w.y, x.z*r*w.z, x.w*r*w.w);
    ((float4*)g_h2)[bj*256 + threadIdx.x] = hv;
}

// ---------------- generic fp32 GEMM: C = A@B (+res) ----------------------
// A [M,K] row-major, B [K,N] row-major. M,N mult of 64, K mult of 16.
__global__ __launch_bounds__(256) void gemm_kernel(
    const float* __restrict__ A, const float* __restrict__ B,
    const float* __restrict__ res, float* __restrict__ C,
    int M, int N, int K)
{
    __shared__ float As[16][64];
    __shared__ float Bs[16][64];
    int tid = threadIdx.x;
    int tx = tid & 15, ty = tid >> 4;
    int row0 = blockIdx.y * 64, col0 = blockIdx.x * 64;
    float acc[4][4] = {};
    for (int k0 = 0; k0 < K; k0 += 16) {
        {
            int r = tid >> 2;                // 0..63
            int k4 = (tid & 3) << 2;         // 0,4,8,12
            float4 a = *(const float4*)&A[(size_t)(row0 + r)*K + k0 + k4];
            As[k4+0][r] = a.x; As[k4+1][r] = a.y; As[k4+2][r] = a.z; As[k4+3][r] = a.w;
        }
        {
            int kk = tid >> 4;               // 0..15
            int c4 = (tid & 15) << 2;
            *(float4*)&Bs[kk][c4] = *(const float4*)&B[(size_t)(k0 + kk)*N + col0 + c4];
        }
        __syncthreads();
        #pragma unroll
        for (int kk = 0; kk < 16; kk++) {
            float ra[4], rb[4];
            #pragma unroll
            for (int i = 0; i < 4; i++) ra[i] = As[kk][ty*4 + i];
            #pragma unroll
            for (int j = 0; j < 4; j++) rb[j] = Bs[kk][tx*4 + j];
            #pragma unroll
            for (int i = 0; i < 4; i++)
                #pragma unroll
                for (int j = 0; j < 4; j++)
                    acc[i][j] = fmaf(ra[i], rb[j], acc[i][j]);
        }
        __syncthreads();
    }
    #pragma unroll
    for (int i = 0; i < 4; i++) {
        size_t r = row0 + ty*4 + i;
        size_t c = col0 + tx*4;
        float4 o = make_float4(acc[i][0], acc[i][1], acc[i][2], acc[i][3]);
        if (res) {
            float4 rr = *(const float4*)&res[r*N + c];
            o.x += rr.x; o.y += rr.y; o.z += rr.z; o.w += rr.w;
        }
        *(float4*)&C[r*N + c] = o;
    }
}

// ---------------- RoPE on q and k (in place) ------------------------------
__global__ void rope_kernel() {
    int i = blockIdx.x * blockDim.x + threadIdx.x;
    const int NPAIR = BB*KK*HEADS*32;
    if (i >= 2*NPAIR) return;
    int which = (i >= NPAIR);
    int r = which ? (i - NPAIR) : i;
    int d  = r & 31;
    int hh = (r >> 5) & 15;
    int j  = (r >> 9) & (KK-1);
    int b  = r >> (9 + 9);   // 32*16*512 = 2^18 per batch
    float* base = which ? g_k : g_q;
    int off = ((b*KK + j)*HEADS + hh)*HDIM;
    float inv = expf(-logf(10000.f) * (float)d / 32.f);
    float pos = (float)g_idx[b*KK + j];
    float ang = pos * inv;
    float c = cosf(ang), s = sinf(ang);
    float x1 = base[off + d];
    float x2 = base[off + d + 32];
    base[off + d]      = x1*c - x2*s;
    base[off + d + 32] = x2*c + x1*s;
}

// ---------------- causal attention: block per (qi, head, batch) ----------
__global__ __launch_bounds__(128) void attn_kernel() {
    __shared__ float Ks[128*65];
    __shared__ float probs[KK];
    __shared__ float qrow[HDIM];
    __shared__ float red[32];
    int qi = blockIdx.x, h = blockIdx.y, b = blockIdx.z;
    int tid = threadIdx.x;
    int nk = qi + 1;
    if (tid < HDIM) qrow[tid] = g_q[((b*KK + qi)*HEADS + h)*HDIM + tid];
    __syncthreads();
    // scores
    for (int t0 = 0; t0 < nk; t0 += 128) {
        int tlen = min(128, nk - t0);
        for (int f = tid; f < tlen*16; f += 128) {
            int r = f >> 4, c4 = (f & 15) << 2;
            float4 kv = *(const float4*)&g_k[((b*KK + t0 + r)*HEADS + h)*HDIM + c4];
            float* dst = &Ks[r*65 + c4];
            dst[0]=kv.x; dst[1]=kv.y; dst[2]=kv.z; dst[3]=kv.w;
        }
        __syncthreads();
        if (tid < tlen) {
            float s = 0.f;
            #pragma unroll
            for (int d2 = 0; d2 < HDIM; d2++) s = fmaf(qrow[d2], Ks[tid*65 + d2], s);
            probs[t0 + tid] = s * 0.125f;
        }
        __syncthreads();
    }
    // softmax
    float m = -1e30f;
    for (int j = tid; j < nk; j += 128) m = fmaxf(m, probs[j]);
    m = blk_max(m, red);
    float ssum = 0.f;
    for (int j = tid; j < nk; j += 128) {
        float e = expf(probs[j] - m);
        probs[j] = e;
        ssum += e;
    }
    float tot = blk_sum(ssum, red);
    float invs = 1.f / tot;
    // o = P @ V
    float oacc = 0.f;
    for (int t0 = 0; t0 < nk; t0 += 128) {
        int tlen = min(128, nk - t0);
        __syncthreads();
        for (int f = tid; f < tlen*16; f += 128) {
            int r = f >> 4, c4 = (f & 15) << 2;
            float4 vv = *(const float4*)&g_v[((b*KK + t0 + r)*HEADS + h)*HDIM + c4];
            float* dst = &Ks[r*65 + c4];
            dst[0]=vv.x; dst[1]=vv.y; dst[2]=vv.z; dst[3]=vv.w;
        }
        __syncthreads();
        if (tid < HDIM) {
            for (int jj = 0; jj < tlen; jj++)
                oacc = fmaf(probs[t0 + jj], Ks[jj*65 + tid], oacc);
        }
    }
    if (tid < HDIM) g_o[((b*KK + qi)*HEADS + h)*HDIM + tid] = oacc * invs;
}

// ---------------- silu(gate) * up, in place into g_gateb ------------------
__global__ void silu_mul_kernel() {
    int i = blockIdx.x * blockDim.x + threadIdx.x;
    const int N4 = BKr*FF/4;
    if (i >= N4) return;
    float4 g = ((const float4*)g_gateb)[i];
    float4 u = ((const float4*)g_upb)[i];
    g.x = g.x / (1.f + expf(-g.x)) * u.x;
    g.y = g.y / (1.f + expf(-g.y)) * u.y;
    g.z = g.z / (1.f + expf(-g.z)) * u.z;
    g.w = g.w / (1.f + expf(-g.w)) * u.w;
    ((float4*)g_gateb)[i] = g;
}

// ---------------- final gated residual scatter ----------------------------
__global__ void scatter_kernel(float* __restrict__ out) {
    int bj = blockIdx.x;
    int b = bj >> 9;
    int row = g_idx[bj];
    float gate = g_gates[bj];
    float4 xs = ((const float4*)g_xsel)[bj*256 + threadIdx.x];
    float4 bo = ((const float4*)g_bo)[bj*256 + threadIdx.x];
    float4 o;
    o.x = xs.x + gate*(bo.x - xs.x);
    o.y = xs.y + gate*(bo.y - xs.y);
    o.z = xs.z + gate*(bo.z - xs.z);
    o.w = xs.w + gate*(bo.w - xs.w);
    ((float4*)out)[((size_t)(b*TT + row))*256 + threadIdx.x] = o;
}

// ---------------- launch ---------------------------------------------------
extern "C" void kernel_launch(void* const* d_in, const int* in_sizes, int n_in,
                              void* d_out, int out_size) {
    const float* hs  = (const float*)d_in[0];
    const float* wr  = (const float*)d_in[1];
    const float* wq  = (const float*)d_in[2];
    const float* wk  = (const float*)d_in[3];
    const float* wv  = (const float*)d_in[4];
    const float* wo  = (const float*)d_in[5];
    const float* ln1 = (const float*)d_in[6];
    const float* ln2 = (const float*)d_in[7];
    const float* wg  = (const float*)d_in[8];
    const float* wu  = (const float*)d_in[9];
    const float* wd  = (const float*)d_in[10];
    float* out = (float*)d_out;

    float *p_h, *p_xsel, *p_q, *p_k, *p_v, *p_o, *p_x1, *p_h2, *p_gate, *p_up, *p_bo;
    cudaGetSymbolAddress((void**)&p_h,    g_h);
    cudaGetSymbolAddress((void**)&p_xsel, g_xsel);
    cudaGetSymbolAddress((void**)&p_q,    g_q);
    cudaGetSymbolAddress((void**)&p_k,    g_k);
    cudaGetSymbolAddress((void**)&p_v,    g_v);
    cudaGetSymbolAddress((void**)&p_o,    g_o);
    cudaGetSymbolAddress((void**)&p_x1,   g_x1);
    cudaGetSymbolAddress((void**)&p_h2,   g_h2);
    cudaGetSymbolAddress((void**)&p_gate, g_gateb);
    cudaGetSymbolAddress((void**)&p_up,   g_upb);
    cudaGetSymbolAddress((void**)&p_bo,   g_bo);

    // new_states base = hidden_states
    cudaMemcpyAsync(out, hs, (size_t)BT*DD*sizeof(float), cudaMemcpyDeviceToDevice);

    router_kernel<<<BT/8, 256>>>(hs, wr);
    topk_kernel<<<BB, 1024>>>();
    aux_kernel<<<1, 1024>>>(out, out_size - 1);
    gather_rms1<<<BKr, 256>>>(hs, ln1);

    gemm_kernel<<<dim3(DD/64, BKr/64), 256>>>(p_h, wq, nullptr, p_q, BKr, DD, DD);
    gemm_kernel<<<dim3(DD/64, BKr/64), 256>>>(p_h, wk, nullptr, p_k, BKr, DD, DD);
    gemm_kernel<<<dim3(DD/64, BKr/64), 256>>>(p_h, wv, nullptr, p_v, BKr, DD, DD);

    rope_kernel<<<(2*BB*KK*HEADS*32 + 255)/256, 256>>>();

    attn_kernel<<<dim3(KK, HEADS, BB), 128>>>();

    gemm_kernel<<<dim3(DD/64, BKr/64), 256>>>(p_o, wo, p_xsel, p_x1, BKr, DD, DD);
    rms2_kernel<<<BKr, 256>>>(ln2);

    gemm_kernel<<<dim3(FF/64, BKr/64), 256>>>(p_h2, wg, nullptr, p_gate, BKr, FF, DD);
    gemm_kernel<<<dim3(FF/64, BKr/64), 256>>>(p_h2, wu, nullptr, p_up,   BKr, FF, DD);
    silu_mul_kernel<<<(BKr*FF/4 + 255)/256, 256>>>();
    gemm_kernel<<<dim3(DD/64, BKr/64), 256>>>(p_gate, wd, p_x1, p_bo, BKr, DD, FF);

    scatter_kernel<<<BKr, 256>>>(out);
}

// round 2
// speedup vs baseline: 1.3296x; 1.3296x over previous
#include <cuda_runtime.h>
#include <math.h>

#define BB 4
#define TT 4096
#define DD 1024
#define HEADS 16
#define HDIM 64
#define FF 4096
#define KK 512
#define BT (BB*TT)      // 16384
#define BKr (BB*KK)     // 2048 selected rows total

// ---------------- scratch (static device globals; no cudaMalloc allowed) ----
__device__ float g_logits[BT];
__device__ int   g_idx[BKr];
__device__ float g_gates[BKr];
__device__ float g_xsel[BKr*DD];
__device__ float g_h[BKr*DD];
__device__ float g_q[BKr*DD];
__device__ float g_k[BKr*DD];
__device__ float g_v[BKr*DD];
__device__ float g_o[BKr*DD];
__device__ float g_x1[BKr*DD];
__device__ float g_h2[BKr*DD];
__device__ float g_gateb[BKr*FF];
__device__ float g_upb[BKr*FF];
__device__ float g_bo[BKr*DD];

// ---------------- block reduction helpers --------------------------------
__device__ __forceinline__ float blk_sum(float v, float* red) {
    int lane = threadIdx.x & 31, w = threadIdx.x >> 5;
    #pragma unroll
    for (int o = 16; o; o >>= 1) v += __shfl_down_sync(0xffffffffu, v, o);
    if (lane == 0) red[w] = v;
    __syncthreads();
    int nw = (blockDim.x + 31) >> 5;
    if (threadIdx.x < 32) {
        float t = (threadIdx.x < nw) ? red[threadIdx.x] : 0.f;
        #pragma unroll
        for (int o = 16; o; o >>= 1) t += __shfl_down_sync(0xffffffffu, t, o);
        if (threadIdx.x == 0) red[0] = t;
    }
    __syncthreads();
    float r = red[0];
    __syncthreads();
    return r;
}

// ---------------- router logits: one warp per token ----------------------
__global__ void router_kernel(const float* __restrict__ hs, const float* __restrict__ wr) {
    int warp = (blockIdx.x * blockDim.x + threadIdx.x) >> 5;
    int lane = threadIdx.x & 31;
    if (warp >= BT) return;
    const float4* row = (const float4*)(hs + (size_t)warp * DD);
    const float4* w   = (const float4*)wr;
    float s = 0.f;
    #pragma unroll
    for (int it = 0; it < 8; it++) {
        float4 a = row[lane + 32 * it];
        float4 b = w[lane + 32 * it];
        s += a.x*b.x + a.y*b.y + a.z*b.z + a.w*b.w;
    }
    #pragma unroll
    for (int o = 16; o; o >>= 1) s += __shfl_down_sync(0xffffffffu, s, o);
    if (lane == 0) g_logits[warp] = s;
}

// ---------------- top-k via full bitonic sort (block per batch) ----------
__global__ void topk_kernel() {
    __shared__ float vals[TT];
    __shared__ int   inds[TT];
    int b = blockIdx.x;
    int tid = threadIdx.x;   // 1024
    for (int i = tid; i < TT; i += 1024) { vals[i] = g_logits[b*TT + i]; inds[i] = i; }
    __syncthreads();
    for (int k = 2; k <= TT; k <<= 1) {
        for (int j = k >> 1; j > 0; j >>= 1) {
            for (int i = tid; i < TT; i += 1024) {
                int ixj = i ^ j;
                if (ixj > i) {
                    float va = vals[i], vb = vals[ixj];
                    int ia = inds[i], ib = inds[ixj];
                    bool a_first = (va > vb) || (va == vb && ia < ib);
                    bool desc = ((i & k) == 0);
                    if (desc ? !a_first : a_first) {
                        vals[i] = vb; vals[ixj] = va;
                        inds[i] = ib; inds[ixj] = ia;
                    }
                }
            }
            __syncthreads();
        }
    }
    for (int k = 2; k <= KK; k <<= 1) {
        for (int j = k >> 1; j > 0; j >>= 1) {
            if (tid < KK) {
                int i = tid, ixj = i ^ j;
                if (ixj > i) {
                    int a = inds[i], c = inds[ixj];
                    bool asc = ((i & k) == 0);
                    if (asc ? (a > c) : (a < c)) { inds[i] = c; inds[ixj] = a; }
                }
            }
            __syncthreads();
        }
    }
    if (tid < KK) {
        int id = inds[tid];
        g_idx[b*KK + tid] = id;
        float l = g_logits[b*TT + id];
        g_gates[b*KK + tid] = 1.f / (1.f + expf(-l));
    }
}

// ---------------- aux loss: single block, deterministic ------------------
__global__ void aux_kernel(float* __restrict__ out, int aux_off) {
    __shared__ float red[32];
    float s = 0.f;
    for (int i = threadIdx.x; i < BT; i += blockDim.x) {
        float l = g_logits[i];
        s += fmaxf(l, 0.f) + log1pf(expf(-fabsf(l)));
    }
    for (int i = threadIdx.x; i < BKr; i += blockDim.x) {
        int b = i >> 9;
        s -= g_logits[b*TT + g_idx[i]];
    }
    float tot = blk_sum(s, red);
    if (threadIdx.x == 0) out[aux_off] = tot * (0.01f / (float)BT);
}

// ---------------- gather + rmsnorm1 (block per selected row) -------------
__global__ void gather_rms1(const float* __restrict__ hs, const float* __restrict__ ln1) {
    __shared__ float red[32];
    int bj = blockIdx.x;
    int b = bj >> 9;
    int row = g_idx[bj];
    const float4* src = (const float4*)(hs + ((size_t)(b*TT + row)) * DD);
    float4 x = src[threadIdx.x];
    float ss = x.x*x.x + x.y*x.y + x.z*x.z + x.w*x.w;
    float tot = blk_sum(ss, red);
    float r = rsqrtf(tot / (float)DD + 1e-6f);
    ((float4*)g_xsel)[bj*256 + threadIdx.x] = x;
    float4 w = ((const float4*)ln1)[threadIdx.x];
    float4 hv = make_float4(x.x*r*w.x, x.y*r*w.y, x.z*r*w.z, x.w*r*w.w);
    ((float4*)g_h)[bj*256 + threadIdx.x] = hv;
}

// ---------------- rmsnorm2: g_x1 -> g_h2 ---------------------------------
__global__ void rms2_kernel(const float* __restrict__ ln2) {
    __shared__ float red[32];
    int bj = blockIdx.x;
    float4 x = ((const float4*)g_x1)[bj*256 + threadIdx.x];
    float ss = x.x*x.x + x.y*x.y + x.z*x.z + x.w*x.w;
    float tot = blk_sum(ss, red);
    float r = rsqrtf(tot / (float)DD + 1e-6f);
    float4 w = ((const float4*)ln2)[threadIdx.x];
    float4 hv = make_float4(x.x*r*w.x, x.y*r*w.y, x.z*r*w.z, x.w*r*w.w);
    ((float4*)g_h2)[bj*256 + threadIdx.x] = hv;
}

// ---------------- fp32 GEMM v2: 128x128 tile, 8x8/thread, double-buffered -
// A [M,K] row-major, B [K,N] row-major. M,N mult of 128, K mult of 16.
__global__ __launch_bounds__(256, 2) void gemm_kernel(
    const float* __restrict__ A, const float* __restrict__ B,
    const float* __restrict__ res, float* __restrict__ C,
    int M, int N, int K)
{
    __shared__ float As[2][16][128];
    __shared__ float Bs[2][16][128];
    int tid = threadIdx.x;
    int tx = tid & 15, ty = tid >> 4;
    int row0 = blockIdx.y * 128, col0 = blockIdx.x * 128;

    int ar = tid >> 1;            // 0..127
    int ak = (tid & 1) * 8;       // 0 or 8
    const float* Ap = A + (size_t)(row0 + ar) * K + ak;
    int bk = tid >> 5;            // 0..7
    int bc = (tid & 31) * 4;
    const float* Bp = B + (size_t)bk * N + col0 + bc;

    float acc[8][8];
    #pragma unroll
    for (int i = 0; i < 8; i++)
        #pragma unroll
        for (int j = 0; j < 8; j++) acc[i][j] = 0.f;

    int nt = K / 16;
    float4 a0 = *(const float4*)(Ap);
    float4 a1 = *(const float4*)(Ap + 4);
    float4 b0 = *(const float4*)(Bp);
    float4 b1 = *(const float4*)(Bp + (size_t)8 * N);

    int buf = 0;
    As[0][ak+0][ar] = a0.x; As[0][ak+1][ar] = a0.y; As[0][ak+2][ar] = a0.z; As[0][ak+3][ar] = a0.w;
    As[0][ak+4][ar] = a1.x; As[0][ak+5][ar] = a1.y; As[0][ak+6][ar] = a1.z; As[0][ak+7][ar] = a1.w;
    *(float4*)&Bs[0][bk][bc]   = b0;
    *(float4*)&Bs[0][bk+8][bc] = b1;
    __syncthreads();

    for (int t = 0; t < nt; t++) {
        if (t + 1 < nt) {
            int k0 = (t + 1) * 16;
            a0 = *(const float4*)(Ap + k0);
            a1 = *(const float4*)(Ap + k0 + 4);
            b0 = *(const float4*)(Bp + (size_t)k0 * N);
            b1 = *(const float4*)(Bp + (size_t)(k0 + 8) * N);
        }
        #pragma unroll
        for (int kk = 0; kk < 16; kk++) {
            float4 xa0 = *(const float4*)&As[buf][kk][ty*4];
            float4 xa1 = *(const float4*)&As[buf][kk][64 + ty*4];
            float4 xb0 = *(const float4*)&Bs[buf][kk][tx*4];
            float4 xb1 = *(const float4*)&Bs[buf][kk][64 + tx*4];
            float af[8] = {xa0.x, xa0.y, xa0.z, xa0.w, xa1.x, xa1.y, xa1.z, xa1.w};
            float bf[8] = {xb0.x, xb0.y, xb0.z, xb0.w, xb1.x, xb1.y, xb1.z, xb1.w};
            #pragma unroll
            for (int i = 0; i < 8; i++)
                #pragma unroll
                for (int j = 0; j < 8; j++)
                    acc[i][j] = fmaf(af[i], bf[j], acc[i][j]);
        }
        if (t + 1 < nt) {
            buf ^= 1;
            As[buf][ak+0][ar] = a0.x; As[buf][ak+1][ar] = a0.y; As[buf][ak+2][ar] = a0.z; As[buf][ak+3][ar] = a0.w;
            As[buf][ak+4][ar] = a1.x; As[buf][ak+5][ar] = a1.y; As[buf][ak+6][ar] = a1.z; As[buf][ak+7][ar] = a1.w;
            *(float4*)&Bs[buf][bk][bc]   = b0;
            *(float4*)&Bs[buf][bk+8][bc] = b1;
        }
        __syncthreads();
    }

    #pragma unroll
    for (int ih = 0; ih < 2; ih++) {
        #pragma unroll
        for (int i = 0; i < 4; i++) {
            size_t r = row0 + ih*64 + ty*4 + i;
            #pragma unroll
            for (int jh = 0; jh < 2; jh++) {
                size_t c = col0 + jh*64 + tx*4;
                float4 o = make_float4(acc[ih*4+i][jh*4+0], acc[ih*4+i][jh*4+1],
                                       acc[ih*4+i][jh*4+2], acc[ih*4+i][jh*4+3]);
                if (res) {
                    float4 rr = *(const float4*)&res[r*N + c];
                    o.x += rr.x; o.y += rr.y; o.z += rr.z; o.w += rr.w;
                }
                *(float4*)&C[r*N + c] = o;
            }
        }
    }
}

// ---------------- RoPE on q and k (in place) ------------------------------
__global__ void rope_kernel() {
    int i = blockIdx.x * blockDim.x + threadIdx.x;
    const int NPAIR = BB*KK*HEADS*32;
    if (i >= 2*NPAIR) return;
    int which = (i >= NPAIR);
    int r = which ? (i - NPAIR) : i;
    int d  = r & 31;
    int hh = (r >> 5) & 15;
    int j  = (r >> 9) & (KK-1);
    int b  = r >> (9 + 9);
    float* base = which ? g_k : g_q;
    int off = ((b*KK + j)*HEADS + hh)*HDIM;
    float inv = expf(-logf(10000.f) * (float)d / 32.f);
    float pos = (float)g_idx[b*KK + j];
    float ang = pos * inv;
    float c = cosf(ang), s = sinf(ang);
    float x1 = base[off + d];
    float x2 = base[off + d + 32];
    base[off + d]      = x1*c - x2*s;
    base[off + d + 32] = x2*c + x1*s;
}

// ---------------- flash attention: block per (q-tile 64, head, batch) ----
__global__ __launch_bounds__(256) void attn_kernel() {
    __shared__ float Qs[64*68];
    __shared__ float Ks[64*68];
    __shared__ float Vs[64*68];
    __shared__ float ps[8*8*64];
    int qt = blockIdx.x, h = blockIdx.y, b = blockIdx.z;
    int tid = threadIdx.x, w = tid >> 5, lane = tid & 31;

    for (int f = tid; f < 64*16; f += 256) {
        int q = f >> 4, d4 = (f & 15) << 2;
        *(float4*)&Qs[q*68 + d4] =
            *(const float4*)&g_q[((size_t)(b*KK + qt*64 + q)*HEADS + h)*HDIM + d4];
    }

    float m[8], l[8], acc0[8], acc1[8];
    #pragma unroll
    for (int i = 0; i < 8; i++) { m[i] = -1e30f; l[i] = 0.f; acc0[i] = 0.f; acc1[i] = 0.f; }

    for (int kt = 0; kt <= qt; kt++) {
        __syncthreads();
        for (int f = tid; f < 64*16; f += 256) {
            int k = f >> 4, d4 = (f & 15) << 2;
            size_t base = ((size_t)(b*KK + kt*64 + k)*HEADS + h)*HDIM + d4;
            *(float4*)&Ks[k*68 + d4] = *(const float4*)&g_k[base];
            *(float4*)&Vs[k*68 + d4] = *(const float4*)&g_v[base];
        }
        __syncthreads();
        bool diag = (kt == qt);
        #pragma unroll
        for (int qq = 0; qq < 8; qq++) {
            int q_loc = w*8 + qq;
            float s0 = 0.f, s1 = 0.f;
            const float4* qp  = (const float4*)&Qs[q_loc*68];
            const float4* k0p = (const float4*)&Ks[lane*68];
            const float4* k1p = (const float4*)&Ks[(lane+32)*68];
            #pragma unroll
            for (int j = 0; j < 16; j++) {
                float4 qv = qp[j], kv0 = k0p[j], kv1 = k1p[j];
                s0 = fmaf(qv.x, kv0.x, s0); s0 = fmaf(qv.y, kv0.y, s0);
                s0 = fmaf(qv.z, kv0.z, s0); s0 = fmaf(qv.w, kv0.w, s0);
                s1 = fmaf(qv.x, kv1.x, s1); s1 = fmaf(qv.y, kv1.y, s1);
                s1 = fmaf(qv.z, kv1.z, s1); s1 = fmaf(qv.w, kv1.w, s1);
            }
            s0 *= 0.125f; s1 *= 0.125f;
            if (diag) {
                if (lane      > q_loc) s0 = -1e30f;
                if (lane + 32 > q_loc) s1 = -1e30f;
            }
            float tmax = fmaxf(s0, s1);
            #pragma unroll
            for (int o = 16; o; o >>= 1) tmax = fmaxf(tmax, __shfl_xor_sync(0xffffffffu, tmax, o));
            float mnew = fmaxf(m[qq], tmax);
            float corr = __expf(m[qq] - mnew);
            float p0 = __expf(s0 - mnew), p1 = __expf(s1 - mnew);
            float rs = p0 + p1;
            #pragma unroll
            for (int o = 16; o; o >>= 1) rs += __shfl_xor_sync(0xffffffffu, rs, o);
            l[qq] = l[qq]*corr + rs;
            acc0[qq] *= corr; acc1[qq] *= corr;
            ps[(w*8+qq)*64 + lane]      = p0;
            ps[(w*8+qq)*64 + lane + 32] = p1;
            m[qq] = mnew;
        }
        __syncwarp();
        #pragma unroll
        for (int qq = 0; qq < 8; qq++) {
            const float* pp = &ps[(w*8+qq)*64];
            float a0 = acc0[qq], a1 = acc1[qq];
            #pragma unroll 8
            for (int k = 0; k < 64; k++) {
                float p = pp[k];
                float2 vv = *(const float2*)&Vs[k*68 + 2*lane];
                a0 = fmaf(p, vv.x, a0);
                a1 = fmaf(p, vv.y, a1);
            }
            acc0[qq] = a0; acc1[qq] = a1;
        }
        __syncwarp();
    }
    #pragma unroll
    for (int qq = 0; qq < 8; qq++) {
        int q_loc = w*8 + qq;
        float inv = 1.f / l[qq];
        float2 o = make_float2(acc0[qq]*inv, acc1[qq]*inv);
        *(float2*)&g_o[((size_t)(b*KK + qt*64 + q_loc)*HEADS + h)*HDIM + 2*lane] = o;
    }
}

// ---------------- silu(gate) * up, in place into g_gateb ------------------
__global__ void silu_mul_kernel() {
    int i = blockIdx.x * blockDim.x + threadIdx.x;
    const int N4 = BKr*FF/4;
    if (i >= N4) return;
    float4 g = ((const float4*)g_gateb)[i];
    float4 u = ((const float4*)g_upb)[i];
    g.x = g.x / (1.f + __expf(-g.x)) * u.x;
    g.y = g.y / (1.f + __expf(-g.y)) * u.y;
    g.z = g.z / (1.f + __expf(-g.z)) * u.z;
    g.w = g.w / (1.f + __expf(-g.w)) * u.w;
    ((float4*)g_gateb)[i] = g;
}

// ---------------- final gated residual scatter ----------------------------
__global__ void scatter_kernel(float* __restrict__ out) {
    int bj = blockIdx.x;
    int b = bj >> 9;
    int row = g_idx[bj];
    float gate = g_gates[bj];
    float4 xs = ((const float4*)g_xsel)[bj*256 + threadIdx.x];
    float4 bo = ((const float4*)g_bo)[bj*256 + threadIdx.x];
    float4 o;
    o.x = xs.x + gate*(bo.x - xs.x);
    o.y = xs.y + gate*(bo.y - xs.y);
    o.z = xs.z + gate*(bo.z - xs.z);
    o.w = xs.w + gate*(bo.w - xs.w);
    ((float4*)out)[((size_t)(b*TT + row))*256 + threadIdx.x] = o;
}

// ---------------- launch ---------------------------------------------------
extern "C" void kernel_launch(void* const* d_in, const int* in_sizes, int n_in,
                              void* d_out, int out_size) {
    const float* hs  = (const float*)d_in[0];
    const float* wr  = (const float*)d_in[1];
    const float* wq  = (const float*)d_in[2];
    const float* wk  = (const float*)d_in[3];
    const float* wv  = (const float*)d_in[4];
    const float* wo  = (const float*)d_in[5];
    const float* ln1 = (const float*)d_in[6];
    const float* ln2 = (const float*)d_in[7];
    const float* wg  = (const float*)d_in[8];
    const float* wu  = (const float*)d_in[9];
    const float* wd  = (const float*)d_in[10];
    float* out = (float*)d_out;

    float *p_h, *p_xsel, *p_q, *p_k, *p_v, *p_o, *p_x1, *p_h2, *p_gate, *p_up, *p_bo;
    cudaGetSymbolAddress((void**)&p_h,    g_h);
    cudaGetSymbolAddress((void**)&p_xsel, g_xsel);
    cudaGetSymbolAddress((void**)&p_q,    g_q);
    cudaGetSymbolAddress((void**)&p_k,    g_k);
    cudaGetSymbolAddress((void**)&p_v,    g_v);
    cudaGetSymbolAddress((void**)&p_o,    g_o);
    cudaGetSymbolAddress((void**)&p_x1,   g_x1);
    cudaGetSymbolAddress((void**)&p_h2,   g_h2);
    cudaGetSymbolAddress((void**)&p_gate, g_gateb);
    cudaGetSymbolAddress((void**)&p_up,   g_upb);
    cudaGetSymbolAddress((void**)&p_bo,   g_bo);

    cudaMemcpyAsync(out, hs, (size_t)BT*DD*sizeof(float), cudaMemcpyDeviceToDevice);

    router_kernel<<<BT/8, 256>>>(hs, wr);
    topk_kernel<<<BB, 1024>>>();
    aux_kernel<<<1, 1024>>>(out, out_size - 1);
    gather_rms1<<<BKr, 256>>>(hs, ln1);

    gemm_kernel<<<dim3(DD/128, BKr/128), 256>>>(p_h, wq, nullptr, p_q, BKr, DD, DD);
    gemm_kernel<<<dim3(DD/128, BKr/128), 256>>>(p_h, wk, nullptr, p_k, BKr, DD, DD);
    gemm_kernel<<<dim3(DD/128, BKr/128), 256>>>(p_h, wv, nullptr, p_v, BKr, DD, DD);

    rope_kernel<<<(2*BB*KK*HEADS*32 + 255)/256, 256>>>();

    attn_kernel<<<dim3(KK/64, HEADS, BB), 256>>>();

    gemm_kernel<<<dim3(DD/128, BKr/128), 256>>>(p_o, wo, p_xsel, p_x1, BKr, DD, DD);
    rms2_kernel<<<BKr, 256>>>(ln2);

    gemm_kernel<<<dim3(FF/128, BKr/128), 256>>>(p_h2, wg, nullptr, p_gate, BKr, FF, DD);
    gemm_kernel<<<dim3(FF/128, BKr/128), 256>>>(p_h2, wu, nullptr, p_up,   BKr, FF, DD);
    silu_mul_kernel<<<(BKr*FF/4 + 255)/256, 256>>>();
    gemm_kernel<<<dim3(DD/128, BKr/128), 256>>>(p_gate, wd, p_x1, p_bo, BKr, DD, FF);

    scatter_kernel<<<BKr, 256>>>(out);
}

// round 3
// speedup vs baseline: 2.6476x; 1.9912x over previous
#include <cuda_runtime.h>
#include <math.h>
#include <stdint.h>

#define BB 4
#define TT 4096
#define DD 1024
#define HEADS 16
#define HDIM 64
#define FF 4096
#define KK 512
#define BT (BB*TT)      // 16384
#define BKr (BB*KK)     // 2048 selected rows total

// ---------------- scratch (static device globals; no cudaMalloc allowed) ----
__device__ float g_logits[BT];
__device__ int   g_idx[BKr];
__device__ float g_gates[BKr];
__device__ float g_xsel[BKr*DD];
__device__ float g_h[BKr*DD];
__device__ float g_q[BKr*DD];
__device__ float g_k[BKr*DD];
__device__ float g_v[BKr*DD];
__device__ float g_o[BKr*DD];
__device__ float g_x1[BKr*DD];
__device__ float g_h2[BKr*DD];
__device__ float g_gateb[BKr*FF];
__device__ float g_upb[BKr*FF];
__device__ float g_bo[BKr*DD];

// ---------------- helpers --------------------------------------------------
__device__ __forceinline__ float blk_sum(float v, float* red) {
    int lane = threadIdx.x & 31, w = threadIdx.x >> 5;
    #pragma unroll
    for (int o = 16; o; o >>= 1) v += __shfl_down_sync(0xffffffffu, v, o);
    if (lane == 0) red[w] = v;
    __syncthreads();
    int nw = (blockDim.x + 31) >> 5;
    if (threadIdx.x < 32) {
        float t = (threadIdx.x < nw) ? red[threadIdx.x] : 0.f;
        #pragma unroll
        for (int o = 16; o; o >>= 1) t += __shfl_down_sync(0xffffffffu, t, o);
        if (threadIdx.x == 0) red[0] = t;
    }
    __syncthreads();
    float r = red[0];
    __syncthreads();
    return r;
}

__device__ __forceinline__ uint32_t f2tf(float x) {
    uint32_t y;
    asm("cvt.rna.tf32.f32 %0, %1;" : "=r"(y) : "f"(x));
    return y;
}

// ---------------- router logits: one warp per token ----------------------
__global__ void router_kernel(const float* __restrict__ hs, const float* __restrict__ wr) {
    int warp = (blockIdx.x * blockDim.x + threadIdx.x) >> 5;
    int lane = threadIdx.x & 31;
    if (warp >= BT) return;
    const float4* row = (const float4*)(hs + (size_t)warp * DD);
    const float4* w   = (const float4*)wr;
    float s = 0.f;
    #pragma unroll
    for (int it = 0; it < 8; it++) {
        float4 a = row[lane + 32 * it];
        float4 b = w[lane + 32 * it];
        s += a.x*b.x + a.y*b.y + a.z*b.z + a.w*b.w;
    }
    #pragma unroll
    for (int o = 16; o; o >>= 1) s += __shfl_down_sync(0xffffffffu, s, o);
    if (lane == 0) g_logits[warp] = s;
}

// ---------------- top-k via full bitonic sort (block per batch) ----------
__global__ void topk_kernel() {
    __shared__ float vals[TT];
    __shared__ int   inds[TT];
    int b = blockIdx.x;
    int tid = threadIdx.x;   // 1024
    for (int i = tid; i < TT; i += 1024) { vals[i] = g_logits[b*TT + i]; inds[i] = i; }
    __syncthreads();
    for (int k = 2; k <= TT; k <<= 1) {
        for (int j = k >> 1; j > 0; j >>= 1) {
            for (int i = tid; i < TT; i += 1024) {
                int ixj = i ^ j;
                if (ixj > i) {
                    float va = vals[i], vb = vals[ixj];
                    int ia = inds[i], ib = inds[ixj];
                    bool a_first = (va > vb) || (va == vb && ia < ib);
                    bool desc = ((i & k) == 0);
                    if (desc ? !a_first : a_first) {
                        vals[i] = vb; vals[ixj] = va;
                        inds[i] = ib; inds[ixj] = ia;
                    }
                }
            }
            __syncthreads();
        }
    }
    for (int k = 2; k <= KK; k <<= 1) {
        for (int j = k >> 1; j > 0; j >>= 1) {
            if (tid < KK) {
                int i = tid, ixj = i ^ j;
                if (ixj > i) {
                    int a = inds[i], c = inds[ixj];
                    bool asc = ((i & k) == 0);
                    if (asc ? (a > c) : (a < c)) { inds[i] = c; inds[ixj] = a; }
                }
            }
            __syncthreads();
        }
    }
    if (tid < KK) {
        int id = inds[tid];
        g_idx[b*KK + tid] = id;
        float l = g_logits[b*TT + id];
        g_gates[b*KK + tid] = 1.f / (1.f + expf(-l));
    }
}

// ---------------- aux loss: single block, deterministic ------------------
__global__ void aux_kernel(float* __restrict__ out, int aux_off) {
    __shared__ float red[32];
    float s = 0.f;
    for (int i = threadIdx.x; i < BT; i += blockDim.x) {
        float l = g_logits[i];
        s += fmaxf(l, 0.f) + log1pf(expf(-fabsf(l)));
    }
    for (int i = threadIdx.x; i < BKr; i += blockDim.x) {
        int b = i >> 9;
        s -= g_logits[b*TT + g_idx[i]];
    }
    float tot = blk_sum(s, red);
    if (threadIdx.x == 0) out[aux_off] = tot * (0.01f / (float)BT);
}

// ---------------- gather + rmsnorm1 (block per selected row) -------------
__global__ void gather_rms1(const float* __restrict__ hs, const float* __restrict__ ln1) {
    __shared__ float red[32];
    int bj = blockIdx.x;
    int b = bj >> 9;
    int row = g_idx[bj];
    const float4* src = (const float4*)(hs + ((size_t)(b*TT + row)) * DD);
    float4 x = src[threadIdx.x];
    float ss = x.x*x.x + x.y*x.y + x.z*x.z + x.w*x.w;
    float tot = blk_sum(ss, red);
    float r = rsqrtf(tot / (float)DD + 1e-6f);
    ((float4*)g_xsel)[bj*256 + threadIdx.x] = x;
    float4 w = ((const float4*)ln1)[threadIdx.x];
    float4 hv = make_float4(x.x*r*w.x, x.y*r*w.y, x.z*r*w.z, x.w*r*w.w);
    ((float4*)g_h)[bj*256 + threadIdx.x] = hv;
}

// ---------------- rmsnorm2: g_x1 -> g_h2 ---------------------------------
__global__ void rms2_kernel(const float* __restrict__ ln2) {
    __shared__ float red[32];
    int bj = blockIdx.x;
    float4 x = ((const float4*)g_x1)[bj*256 + threadIdx.x];
    float ss = x.x*x.x + x.y*x.y + x.z*x.z + x.w*x.w;
    float tot = blk_sum(ss, red);
    float r = rsqrtf(tot / (float)DD + 1e-6f);
    float4 w = ((const float4*)ln2)[threadIdx.x];
    float4 hv = make_float4(x.x*r*w.x, x.y*r*w.y, x.z*r*w.z, x.w*r*w.w);
    ((float4*)g_h2)[bj*256 + threadIdx.x] = hv;
}

// ---------------- TF32 tensor-core GEMM: C = A@B (+res) -------------------
// A [M,K] row-major fp32, B [K,N] row-major fp32. M,N mult of 128, K mult 16.
// 128x128 CTA tile, 8 warps (4m x 2n), warp tile 32x64, mma m16n8k8 tf32.
#define AS_STRIDE 20
#define BS_STRIDE 136
__global__ __launch_bounds__(256) void gemm_tc(
    const float* __restrict__ A, const float* __restrict__ B,
    const float* __restrict__ res, float* __restrict__ C,
    int M, int N, int K)
{
    __shared__ uint32_t As[2][128][AS_STRIDE];   // [m][k] k-slice 16
    __shared__ uint32_t Bs[2][16][BS_STRIDE];    // [k][n]
    int tid = threadIdx.x;
    int w = tid >> 5, lane = tid & 31;
    int wm = w >> 1, wn = w & 1;
    int gid = lane >> 2, tid4 = lane & 3;
    int row0 = blockIdx.y * 128, col0 = blockIdx.x * 128;

    int ar = tid >> 1;            // 0..127
    int ak = (tid & 1) * 8;       // 0 or 8
    const float* Ap = A + (size_t)(row0 + ar) * K + ak;
    int bk = tid >> 5;            // 0..7
    int bc = (tid & 31) * 4;
    const float* Bp = B + (size_t)bk * N + col0 + bc;

    float acc[2][8][4];
    #pragma unroll
    for (int i = 0; i < 2; i++)
        #pragma unroll
        for (int j = 0; j < 8; j++)
            #pragma unroll
            for (int c = 0; c < 4; c++) acc[i][j][c] = 0.f;

    int nt = K / 16;
    float4 pa0 = *(const float4*)(Ap);
    float4 pa1 = *(const float4*)(Ap + 4);
    float4 pb0 = *(const float4*)(Bp);
    float4 pb1 = *(const float4*)(Bp + (size_t)8 * N);

    int buf = 0;
    {
        uint32_t* a = &As[0][ar][ak];
        a[0]=f2tf(pa0.x); a[1]=f2tf(pa0.y); a[2]=f2tf(pa0.z); a[3]=f2tf(pa0.w);
        a[4]=f2tf(pa1.x); a[5]=f2tf(pa1.y); a[6]=f2tf(pa1.z); a[7]=f2tf(pa1.w);
        uint32_t* b0p = &Bs[0][bk][bc];
        b0p[0]=f2tf(pb0.x); b0p[1]=f2tf(pb0.y); b0p[2]=f2tf(pb0.z); b0p[3]=f2tf(pb0.w);
        uint32_t* b1p = &Bs[0][bk+8][bc];
        b1p[0]=f2tf(pb1.x); b1p[1]=f2tf(pb1.y); b1p[2]=f2tf(pb1.z); b1p[3]=f2tf(pb1.w);
    }
    __syncthreads();

    for (int t = 0; t < nt; t++) {
        if (t + 1 < nt) {
            int k0 = (t + 1) * 16;
            pa0 = *(const float4*)(Ap + k0);
            pa1 = *(const float4*)(Ap + k0 + 4);
            pb0 = *(const float4*)(Bp + (size_t)k0 * N);
            pb1 = *(const float4*)(Bp + (size_t)(k0 + 8) * N);
        }
        #pragma unroll
        for (int ks = 0; ks < 2; ks++) {
            int kb = ks * 8;
            uint32_t af[2][4];
            #pragma unroll
            for (int mt = 0; mt < 2; mt++) {
                int rm = wm*32 + mt*16;
                af[mt][0] = As[buf][rm + gid    ][kb + tid4    ];
                af[mt][1] = As[buf][rm + gid + 8][kb + tid4    ];
                af[mt][2] = As[buf][rm + gid    ][kb + tid4 + 4];
                af[mt][3] = As[buf][rm + gid + 8][kb + tid4 + 4];
            }
            uint32_t bf[8][2];
            #pragma unroll
            for (int ntile = 0; ntile < 8; ntile++) {
                int cn = wn*64 + ntile*8 + gid;
                bf[ntile][0] = Bs[buf][kb + tid4    ][cn];
                bf[ntile][1] = Bs[buf][kb + tid4 + 4][cn];
            }
            #pragma unroll
            for (int mt = 0; mt < 2; mt++)
                #pragma unroll
                for (int ntile = 0; ntile < 8; ntile++) {
                    asm volatile(
                        "mma.sync.aligned.m16n8k8.row.col.f32.tf32.tf32.f32 "
                        "{%0,%1,%2,%3}, {%4,%5,%6,%7}, {%8,%9}, {%0,%1,%2,%3};"
                        : "+f"(acc[mt][ntile][0]), "+f"(acc[mt][ntile][1]),
                          "+f"(acc[mt][ntile][2]), "+f"(acc[mt][ntile][3])
                        : "r"(af[mt][0]), "r"(af[mt][1]), "r"(af[mt][2]), "r"(af[mt][3]),
                          "r"(bf[ntile][0]), "r"(bf[ntile][1]));
                }
        }
        if (t + 1 < nt) {
            buf ^= 1;
            uint32_t* a = &As[buf][ar][ak];
            a[0]=f2tf(pa0.x); a[1]=f2tf(pa0.y); a[2]=f2tf(pa0.z); a[3]=f2tf(pa0.w);
            a[4]=f2tf(pa1.x); a[5]=f2tf(pa1.y); a[6]=f2tf(pa1.z); a[7]=f2tf(pa1.w);
            uint32_t* b0p = &Bs[buf][bk][bc];
            b0p[0]=f2tf(pb0.x); b0p[1]=f2tf(pb0.y); b0p[2]=f2tf(pb0.z); b0p[3]=f2tf(pb0.w);
            uint32_t* b1p = &Bs[buf][bk+8][bc];
            b1p[0]=f2tf(pb1.x); b1p[1]=f2tf(pb1.y); b1p[2]=f2tf(pb1.z); b1p[3]=f2tf(pb1.w);
        }
        __syncthreads();
    }

    #pragma unroll
    for (int mt = 0; mt < 2; mt++) {
        int row = row0 + wm*32 + mt*16 + gid;
        #pragma unroll
        for (int ntile = 0; ntile < 8; ntile++) {
            int col = col0 + wn*64 + ntile*8 + tid4*2;
            float2 v0 = make_float2(acc[mt][ntile][0], acc[mt][ntile][1]);
            float2 v1 = make_float2(acc[mt][ntile][2], acc[mt][ntile][3]);
            if (res) {
                float2 r0 = *(const float2*)&res[(size_t)row*N + col];
                float2 r1 = *(const float2*)&res[(size_t)(row+8)*N + col];
                v0.x += r0.x; v0.y += r0.y;
                v1.x += r1.x; v1.y += r1.y;
            }
            *(float2*)&C[(size_t)row*N + col]     = v0;
            *(float2*)&C[(size_t)(row+8)*N + col] = v1;
        }
    }
}

// ---------------- RoPE on q and k (in place) ------------------------------
__global__ void rope_kernel() {
    int i = blockIdx.x * blockDim.x + threadIdx.x;
    const int NPAIR = BB*KK*HEADS*32;
    if (i >= 2*NPAIR) return;
    int which = (i >= NPAIR);
    int r = which ? (i - NPAIR) : i;
    int d  = r & 31;
    int hh = (r >> 5) & 15;
    int j  = (r >> 9) & (KK-1);
    int b  = r >> (9 + 9);
    float* base = which ? g_k : g_q;
    int off = ((b*KK + j)*HEADS + hh)*HDIM;
    float inv = expf(-logf(10000.f) * (float)d / 32.f);
    float pos = (float)g_idx[b*KK + j];
    float ang = pos * inv;
    float c = cosf(ang), s = sinf(ang);
    float x1 = base[off + d];
    float x2 = base[off + d + 32];
    base[off + d]      = x1*c - x2*s;
    base[off + d + 32] = x2*c + x1*s;
}

// ---------------- flash attention: block per (q-tile 64, head, batch) ----
__global__ __launch_bounds__(256) void attn_kernel() {
    __shared__ float Qs[64*68];
    __shared__ float Ks[64*68];
    __shared__ float Vs[64*68];
    __shared__ float ps[8*8*64];
    int qt = blockIdx.x, h = blockIdx.y, b = blockIdx.z;
    int tid = threadIdx.x, w = tid >> 5, lane = tid & 31;

    for (int f = tid; f < 64*16; f += 256) {
        int q = f >> 4, d4 = (f & 15) << 2;
        *(float4*)&Qs[q*68 + d4] =
            *(const float4*)&g_q[((size_t)(b*KK + qt*64 + q)*HEADS + h)*HDIM + d4];
    }

    float m[8], l[8], acc0[8], acc1[8];
    #pragma unroll
    for (int i = 0; i < 8; i++) { m[i] = -1e30f; l[i] = 0.f; acc0[i] = 0.f; acc1[i] = 0.f; }

    for (int kt = 0; kt <= qt; kt++) {
        __syncthreads();
        for (int f = tid; f < 64*16; f += 256) {
            int k = f >> 4, d4 = (f & 15) << 2;
            size_t base = ((size_t)(b*KK + kt*64 + k)*HEADS + h)*HDIM + d4;
            *(float4*)&Ks[k*68 + d4] = *(const float4*)&g_k[base];
            *(float4*)&Vs[k*68 + d4] = *(const float4*)&g_v[base];
        }
        __syncthreads();
        bool diag = (kt == qt);
        #pragma unroll
        for (int qq = 0; qq < 8; qq++) {
            int q_loc = w*8 + qq;
            float s0 = 0.f, s1 = 0.f;
            const float4* qp  = (const float4*)&Qs[q_loc*68];
            const float4* k0p = (const float4*)&Ks[lane*68];
            const float4* k1p = (const float4*)&Ks[(lane+32)*68];
            #pragma unroll
            for (int j = 0; j < 16; j++) {
                float4 qv = qp[j], kv0 = k0p[j], kv1 = k1p[j];
                s0 = fmaf(qv.x, kv0.x, s0); s0 = fmaf(qv.y, kv0.y, s0);
                s0 = fmaf(qv.z, kv0.z, s0); s0 = fmaf(qv.w, kv0.w, s0);
                s1 = fmaf(qv.x, kv1.x, s1); s1 = fmaf(qv.y, kv1.y, s1);
                s1 = fmaf(qv.z, kv1.z, s1); s1 = fmaf(qv.w, kv1.w, s1);
            }
            s0 *= 0.125f; s1 *= 0.125f;
            if (diag) {
                if (lane      > q_loc) s0 = -1e30f;
                if (lane + 32 > q_loc) s1 = -1e30f;
            }
            float tmax = fmaxf(s0, s1);
            #pragma unroll
            for (int o = 16; o; o >>= 1) tmax = fmaxf(tmax, __shfl_xor_sync(0xffffffffu, tmax, o));
            float mnew = fmaxf(m[qq], tmax);
            float corr = __expf(m[qq] - mnew);
            float p0 = __expf(s0 - mnew), p1 = __expf(s1 - mnew);
            float rs = p0 + p1;
            #pragma unroll
            for (int o = 16; o; o >>= 1) rs += __shfl_xor_sync(0xffffffffu, rs, o);
            l[qq] = l[qq]*corr + rs;
            acc0[qq] *= corr; acc1[qq] *= corr;
            ps[(w*8+qq)*64 + lane]      = p0;
            ps[(w*8+qq)*64 + lane + 32] = p1;
            m[qq] = mnew;
        }
        __syncwarp();
        #pragma unroll
        for (int qq = 0; qq < 8; qq++) {
            const float* pp = &ps[(w*8+qq)*64];
            float a0 = acc0[qq], a1 = acc1[qq];
            #pragma unroll 8
            for (int k = 0; k < 64; k++) {
                float p = pp[k];
                float2 vv = *(const float2*)&Vs[k*68 + 2*lane];
                a0 = fmaf(p, vv.x, a0);
                a1 = fmaf(p, vv.y, a1);
            }
            acc0[qq] = a0; acc1[qq] = a1;
        }
        __syncwarp();
    }
    #pragma unroll
    for (int qq = 0; qq < 8; qq++) {
        int q_loc = w*8 + qq;
        float inv = 1.f / l[qq];
        float2 o = make_float2(acc0[qq]*inv, acc1[qq]*inv);
        *(float2*)&g_o[((size_t)(b*KK + qt*64 + q_loc)*HEADS + h)*HDIM + 2*lane] = o;
    }
}

// ---------------- silu(gate) * up, in place into g_gateb ------------------
__global__ void silu_mul_kernel() {
    int i = blockIdx.x * blockDim.x + threadIdx.x;
    const int N4 = BKr*FF/4;
    if (i >= N4) return;
    float4 g = ((const float4*)g_gateb)[i];
    float4 u = ((const float4*)g_upb)[i];
    g.x = g.x / (1.f + __expf(-g.x)) * u.x;
    g.y = g.y / (1.f + __expf(-g.y)) * u.y;
    g.z = g.z / (1.f + __expf(-g.z)) * u.z;
    g.w = g.w / (1.f + __expf(-g.w)) * u.w;
    ((float4*)g_gateb)[i] = g;
}

// ---------------- final gated residual scatter ----------------------------
__global__ void scatter_kernel(float* __restrict__ out) {
    int bj = blockIdx.x;
    int b = bj >> 9;
    int row = g_idx[bj];
    float gate = g_gates[bj];
    float4 xs = ((const float4*)g_xsel)[bj*256 + threadIdx.x];
    float4 bo = ((const float4*)g_bo)[bj*256 + threadIdx.x];
    float4 o;
    o.x = xs.x + gate*(bo.x - xs.x);
    o.y = xs.y + gate*(bo.y - xs.y);
    o.z = xs.z + gate*(bo.z - xs.z);
    o.w = xs.w + gate*(bo.w - xs.w);
    ((float4*)out)[((size_t)(b*TT + row))*256 + threadIdx.x] = o;
}

// ---------------- launch ---------------------------------------------------
extern "C" void kernel_launch(void* const* d_in, const int* in_sizes, int n_in,
                              void* d_out, int out_size) {
    const float* hs  = (const float*)d_in[0];
    const float* wr  = (const float*)d_in[1];
    const float* wq  = (const float*)d_in[2];
    const float* wk  = (const float*)d_in[3];
    const float* wv  = (const float*)d_in[4];
    const float* wo  = (const float*)d_in[5];
    const float* ln1 = (const float*)d_in[6];
    const float* ln2 = (const float*)d_in[7];
    const float* wg  = (const float*)d_in[8];
    const float* wu  = (const float*)d_in[9];
    const float* wd  = (const float*)d_in[10];
    float* out = (float*)d_out;

    float *p_h, *p_xsel, *p_q, *p_k, *p_v, *p_o, *p_x1, *p_h2, *p_gate, *p_up, *p_bo;
    cudaGetSymbolAddress((void**)&p_h,    g_h);
    cudaGetSymbolAddress((void**)&p_xsel, g_xsel);
    cudaGetSymbolAddress((void**)&p_q,    g_q);
    cudaGetSymbolAddress((void**)&p_k,    g_k);
    cudaGetSymbolAddress((void**)&p_v,    g_v);
    cudaGetSymbolAddress((void**)&p_o,    g_o);
    cudaGetSymbolAddress((void**)&p_x1,   g_x1);
    cudaGetSymbolAddress((void**)&p_h2,   g_h2);
    cudaGetSymbolAddress((void**)&p_gate, g_gateb);
    cudaGetSymbolAddress((void**)&p_up,   g_upb);
    cudaGetSymbolAddress((void**)&p_bo,   g_bo);

    cudaMemcpyAsync(out, hs, (size_t)BT*DD*sizeof(float), cudaMemcpyDeviceToDevice);

    router_kernel<<<BT/8, 256>>>(hs, wr);
    topk_kernel<<<BB, 1024>>>();
    aux_kernel<<<1, 1024>>>(out, out_size - 1);
    gather_rms1<<<BKr, 256>>>(hs, ln1);

    gemm_tc<<<dim3(DD/128, BKr/128), 256>>>(p_h, wq, nullptr, p_q, BKr, DD, DD);
    gemm_tc<<<dim3(DD/128, BKr/128), 256>>>(p_h, wk, nullptr, p_k, BKr, DD, DD);
    gemm_tc<<<dim3(DD/128, BKr/128), 256>>>(p_h, wv, nullptr, p_v, BKr, DD, DD);

    rope_kernel<<<(2*BB*KK*HEADS*32 + 255)/256, 256>>>();

    attn_kernel<<<dim3(KK/64, HEADS, BB), 256>>>();

    gemm_tc<<<dim3(DD/128, BKr/128), 256>>>(p_o, wo, p_xsel, p_x1, BKr, DD, DD);
    rms2_kernel<<<BKr, 256>>>(ln2);

    gemm_tc<<<dim3(FF/128, BKr/128), 256>>>(p_h2, wg, nullptr, p_gate, BKr, FF, DD);
    gemm_tc<<<dim3(FF/128, BKr/128), 256>>>(p_h2, wu, nullptr, p_up,   BKr, FF, DD);
    silu_mul_kernel<<<(BKr*FF/4 + 255)/256, 256>>>();
    gemm_tc<<<dim3(DD/128, BKr/128), 256>>>(p_gate, wd, p_x1, p_bo, BKr, DD, FF);

    scatter_kernel<<<BKr, 256>>>(out);
}

// round 4
// speedup vs baseline: 4.0394x; 1.5257x over previous
#include <cuda_runtime.h>
#include <math.h>
#include <stdint.h>

#define BB 4
#define TT 4096
#define DD 1024
#define HEADS 16
#define HDIM 64
#define FF 4096
#define KK 512
#define BT (BB*TT)      // 16384
#define BKr (BB*KK)     // 2048 selected rows total

// ---------------- scratch ----------------------------------------------------
__device__ float g_logits[BT];
__device__ int   g_idx[BKr];
__device__ float g_gates[BKr];
__device__ float g_xsel[BKr*DD];
__device__ float g_h[BKr*DD];
__device__ float g_q[BKr*DD];
__device__ float g_k[BKr*DD];
__device__ float g_v[BKr*DD];
__device__ float g_o[BKr*DD];
__device__ float g_x1[BKr*DD];
__device__ float g_h2[BKr*DD];
__device__ float g_gateb[BKr*FF];
__device__ float g_upb[BKr*FF];
__device__ float g_bo[BKr*DD];

// ---------------- helpers ----------------------------------------------------
__device__ __forceinline__ float blk_sum(float v, float* red) {
    int lane = threadIdx.x & 31, w = threadIdx.x >> 5;
    #pragma unroll
    for (int o = 16; o; o >>= 1) v += __shfl_down_sync(0xffffffffu, v, o);
    if (lane == 0) red[w] = v;
    __syncthreads();
    int nw = (blockDim.x + 31) >> 5;
    if (threadIdx.x < 32) {
        float t = (threadIdx.x < nw) ? red[threadIdx.x] : 0.f;
        #pragma unroll
        for (int o = 16; o; o >>= 1) t += __shfl_down_sync(0xffffffffu, t, o);
        if (threadIdx.x == 0) red[0] = t;
    }
    __syncthreads();
    float r = red[0];
    __syncthreads();
    return r;
}

__device__ __forceinline__ uint32_t f2tf(float x) {
    uint32_t y;
    asm("cvt.rna.tf32.f32 %0, %1;" : "=r"(y) : "f"(x));
    return y;
}

__device__ __forceinline__ void cp16(void* s, const void* g) {
    uint32_t sa = (uint32_t)__cvta_generic_to_shared(s);
    asm volatile("cp.async.cg.shared.global [%0], [%1], 16;" :: "r"(sa), "l"(g));
}

#define MMA_TF32(d0,d1,d2,d3,a0,a1,a2,a3,b0,b1) \
    asm volatile("mma.sync.aligned.m16n8k8.row.col.f32.tf32.tf32.f32 " \
        "{%0,%1,%2,%3}, {%4,%5,%6,%7}, {%8,%9}, {%0,%1,%2,%3};" \
        : "+f"(d0), "+f"(d1), "+f"(d2), "+f"(d3) \
        : "r"(a0), "r"(a1), "r"(a2), "r"(a3), "r"(b0), "r"(b1))

// ---------------- router logits: one warp per token ----------------------
__global__ void router_kernel(const float* __restrict__ hs, const float* __restrict__ wr) {
    int warp = (blockIdx.x * blockDim.x + threadIdx.x) >> 5;
    int lane = threadIdx.x & 31;
    if (warp >= BT) return;
    const float4* row = (const float4*)(hs + (size_t)warp * DD);
    const float4* w   = (const float4*)wr;
    float s = 0.f;
    #pragma unroll
    for (int it = 0; it < 8; it++) {
        float4 a = row[lane + 32 * it];
        float4 b = w[lane + 32 * it];
        s += a.x*b.x + a.y*b.y + a.z*b.z + a.w*b.w;
    }
    #pragma unroll
    for (int o = 16; o; o >>= 1) s += __shfl_down_sync(0xffffffffu, s, o);
    if (lane == 0) g_logits[warp] = s;
}

// ---------------- top-k via full bitonic sort (block per batch) ----------
__global__ void topk_kernel() {
    __shared__ float vals[TT];
    __shared__ int   inds[TT];
    int b = blockIdx.x;
    int tid = threadIdx.x;   // 1024
    for (int i = tid; i < TT; i += 1024) { vals[i] = g_logits[b*TT + i]; inds[i] = i; }
    __syncthreads();
    for (int k = 2; k <= TT; k <<= 1) {
        for (int j = k >> 1; j > 0; j >>= 1) {
            for (int i = tid; i < TT; i += 1024) {
                int ixj = i ^ j;
                if (ixj > i) {
                    float va = vals[i], vb = vals[ixj];
                    int ia = inds[i], ib = inds[ixj];
                    bool a_first = (va > vb) || (va == vb && ia < ib);
                    bool desc = ((i & k) == 0);
                    if (desc ? !a_first : a_first) {
                        vals[i] = vb; vals[ixj] = va;
                        inds[i] = ib; inds[ixj] = ia;
                    }
                }
            }
            __syncthreads();
        }
    }
    for (int k = 2; k <= KK; k <<= 1) {
        for (int j = k >> 1; j > 0; j >>= 1) {
            if (tid < KK) {
                int i = tid, ixj = i ^ j;
                if (ixj > i) {
                    int a = inds[i], c = inds[ixj];
                    bool asc = ((i & k) == 0);
                    if (asc ? (a > c) : (a < c)) { inds[i] = c; inds[ixj] = a; }
                }
            }
            __syncthreads();
        }
    }
    if (tid < KK) {
        int id = inds[tid];
        g_idx[b*KK + tid] = id;
        float l = g_logits[b*TT + id];
        g_gates[b*KK + tid] = 1.f / (1.f + expf(-l));
    }
}

// ---------------- aux loss ------------------------------------------------
__global__ void aux_kernel(float* __restrict__ out, int aux_off) {
    __shared__ float red[32];
    float s = 0.f;
    for (int i = threadIdx.x; i < BT; i += blockDim.x) {
        float l = g_logits[i];
        s += fmaxf(l, 0.f) + log1pf(expf(-fabsf(l)));
    }
    for (int i = threadIdx.x; i < BKr; i += blockDim.x) {
        int b = i >> 9;
        s -= g_logits[b*TT + g_idx[i]];
    }
    float tot = blk_sum(s, red);
    if (threadIdx.x == 0) out[aux_off] = tot * (0.01f / (float)BT);
}

// ---------------- gather + rmsnorm1 ---------------------------------------
__global__ void gather_rms1(const float* __restrict__ hs, const float* __restrict__ ln1) {
    __shared__ float red[32];
    int bj = blockIdx.x;
    int b = bj >> 9;
    int row = g_idx[bj];
    const float4* src = (const float4*)(hs + ((size_t)(b*TT + row)) * DD);
    float4 x = src[threadIdx.x];
    float ss = x.x*x.x + x.y*x.y + x.z*x.z + x.w*x.w;
    float tot = blk_sum(ss, red);
    float r = rsqrtf(tot / (float)DD + 1e-6f);
    ((float4*)g_xsel)[bj*256 + threadIdx.x] = x;
    float4 w = ((const float4*)ln1)[threadIdx.x];
    float4 hv = make_float4(x.x*r*w.x, x.y*r*w.y, x.z*r*w.z, x.w*r*w.w);
    ((float4*)g_h)[bj*256 + threadIdx.x] = hv;
}

// ---------------- rmsnorm2 -------------------------------------------------
__global__ void rms2_kernel(const float* __restrict__ ln2) {
    __shared__ float red[32];
    int bj = blockIdx.x;
    float4 x = ((const float4*)g_x1)[bj*256 + threadIdx.x];
    float ss = x.x*x.x + x.y*x.y + x.z*x.z + x.w*x.w;
    float tot = blk_sum(ss, red);
    float r = rsqrtf(tot / (float)DD + 1e-6f);
    float4 w = ((const float4*)ln2)[threadIdx.x];
    float4 hv = make_float4(x.x*r*w.x, x.y*r*w.y, x.z*r*w.z, x.w*r*w.w);
    ((float4*)g_h2)[bj*256 + threadIdx.x] = hv;
}

// ---------------- TF32 tensor-core GEMM with cp.async ----------------------
// C_z = A @ B_z (+res). blockIdx.z selects B/C pair (fused QKV / gate-up).
// 128x128 CTA tile, K-slice 32, double-buffered cp.async.
#define ASTR 36
#define BSTR 136
__global__ __launch_bounds__(256) void gemm_tc(
    const float* __restrict__ A,
    const float* __restrict__ B0, const float* __restrict__ B1, const float* __restrict__ B2,
    const float* __restrict__ res,
    float* __restrict__ C0, float* __restrict__ C1, float* __restrict__ C2,
    int M, int N, int K)
{
    const float* B = (blockIdx.z == 0) ? B0 : (blockIdx.z == 1 ? B1 : B2);
    float*       C = (blockIdx.z == 0) ? C0 : (blockIdx.z == 1 ? C1 : C2);

    __shared__ float As[2][128][ASTR];
    __shared__ float Bs[2][32][BSTR];
    int tid = threadIdx.x;
    int w = tid >> 5, lane = tid & 31;
    int wm = w >> 1, wn = w & 1;
    int gid = lane >> 2, tid4 = lane & 3;
    int row0 = blockIdx.y * 128, col0 = blockIdx.x * 128;

    int arr = tid >> 3;          // 0..31 (row block for A copy)
    int arc = (tid & 7) * 4;     // col within 32-float slice
    int brk = tid >> 5;          // 0..7 (k for B copy)
    int brc = (tid & 31) * 4;

    float acc[2][8][4];
    #pragma unroll
    for (int i = 0; i < 2; i++)
        #pragma unroll
        for (int j = 0; j < 8; j++)
            #pragma unroll
            for (int c = 0; c < 4; c++) acc[i][j][c] = 0.f;

    int nt = K / 32;

    // prologue: issue tile 0
    #pragma unroll
    for (int p = 0; p < 4; p++)
        cp16(&As[0][arr + p*32][arc], &A[(size_t)(row0 + arr + p*32)*K + arc]);
    #pragma unroll
    for (int p = 0; p < 4; p++)
        cp16(&Bs[0][brk + p*8][brc], &B[(size_t)(brk + p*8)*N + col0 + brc]);
    asm volatile("cp.async.commit_group;");

    int buf = 0;
    for (int t = 0; t < nt; t++) {
        if (t + 1 < nt) {
            int k0 = (t + 1) * 32;
            #pragma unroll
            for (int p = 0; p < 4; p++)
                cp16(&As[buf^1][arr + p*32][arc], &A[(size_t)(row0 + arr + p*32)*K + k0 + arc]);
            #pragma unroll
            for (int p = 0; p < 4; p++)
                cp16(&Bs[buf^1][brk + p*8][brc], &B[(size_t)(k0 + brk + p*8)*N + col0 + brc]);
            asm volatile("cp.async.commit_group;");
            asm volatile("cp.async.wait_group 1;");
        } else {
            asm volatile("cp.async.wait_group 0;");
        }
        __syncthreads();

        #pragma unroll
        for (int ks = 0; ks < 4; ks++) {
            int kb = ks * 8;
            uint32_t af[2][4];
            #pragma unroll
            for (int mt = 0; mt < 2; mt++) {
                int rm = wm*32 + mt*16;
                af[mt][0] = f2tf(As[buf][rm + gid    ][kb + tid4    ]);
                af[mt][1] = f2tf(As[buf][rm + gid + 8][kb + tid4    ]);
                af[mt][2] = f2tf(As[buf][rm + gid    ][kb + tid4 + 4]);
                af[mt][3] = f2tf(As[buf][rm + gid + 8][kb + tid4 + 4]);
            }
            #pragma unroll
            for (int n2 = 0; n2 < 8; n2++) {
                int cn = wn*64 + n2*8 + gid;
                uint32_t b0 = f2tf(Bs[buf][kb + tid4    ][cn]);
                uint32_t b1 = f2tf(Bs[buf][kb + tid4 + 4][cn]);
                MMA_TF32(acc[0][n2][0], acc[0][n2][1], acc[0][n2][2], acc[0][n2][3],
                         af[0][0], af[0][1], af[0][2], af[0][3], b0, b1);
                MMA_TF32(acc[1][n2][0], acc[1][n2][1], acc[1][n2][2], acc[1][n2][3],
                         af[1][0], af[1][1], af[1][2], af[1][3], b0, b1);
            }
        }
        __syncthreads();
        buf ^= 1;
    }

    #pragma unroll
    for (int mt = 0; mt < 2; mt++) {
        int row = row0 + wm*32 + mt*16 + gid;
        #pragma unroll
        for (int n2 = 0; n2 < 8; n2++) {
            int col = col0 + wn*64 + n2*8 + tid4*2;
            float2 v0 = make_float2(acc[mt][n2][0], acc[mt][n2][1]);
            float2 v1 = make_float2(acc[mt][n2][2], acc[mt][n2][3]);
            if (res) {
                float2 r0 = *(const float2*)&res[(size_t)row*N + col];
                float2 r1 = *(const float2*)&res[(size_t)(row+8)*N + col];
                v0.x += r0.x; v0.y += r0.y;
                v1.x += r1.x; v1.y += r1.y;
            }
            *(float2*)&C[(size_t)row*N + col]     = v0;
            *(float2*)&C[(size_t)(row+8)*N + col] = v1;
        }
    }
}

// ---------------- RoPE on q and k (in place) ------------------------------
__global__ void rope_kernel() {
    int i = blockIdx.x * blockDim.x + threadIdx.x;
    const int NPAIR = BB*KK*HEADS*32;
    if (i >= 2*NPAIR) return;
    int which = (i >= NPAIR);
    int r = which ? (i - NPAIR) : i;
    int d  = r & 31;
    int hh = (r >> 5) & 15;
    int j  = (r >> 9) & (KK-1);
    int b  = r >> (9 + 9);
    float* base = which ? g_k : g_q;
    int off = ((b*KK + j)*HEADS + hh)*HDIM;
    float inv = expf(-logf(10000.f) * (float)d / 32.f);
    float pos = (float)g_idx[b*KK + j];
    float ang = pos * inv;
    float c = cosf(ang), s = sinf(ang);
    float x1 = base[off + d];
    float x2 = base[off + d + 32];
    base[off + d]      = x1*c - x2*s;
    base[off + d + 32] = x2*c + x1*s;
}

// ---------------- tensor-core flash attention ------------------------------
// block = (q-tile 64, head, batch); 128 threads = 4 warps, warp owns 16 q rows.
__global__ __launch_bounds__(128) void attn_tc() {
    __shared__ float Qs[64][68];
    __shared__ float Ks[64][68];
    __shared__ float Vs[64][72];
    __shared__ float Ps[4][16][68];
    int qt = blockIdx.x, h = blockIdx.y, b = blockIdx.z;
    int tid = threadIdx.x, w = tid >> 5, lane = tid & 31;
    int gid = lane >> 2, tid4 = lane & 3;

    for (int f = tid; f < 64*16; f += 128) {
        int q = f >> 4, d4 = (f & 15) << 2;
        *(float4*)&Qs[q][d4] =
            *(const float4*)&g_q[((size_t)((b*KK + qt*64 + q)*HEADS + h))*HDIM + d4];
    }

    int r0g = qt*64 + w*16 + gid;    // global (in-sequence) row for c0/c1
    int r1g = r0g + 8;               // for c2/c3

    float m0 = -1e30f, m1 = -1e30f, l0 = 0.f, l1 = 0.f;
    float oa[8][4];
    #pragma unroll
    for (int n2 = 0; n2 < 8; n2++)
        #pragma unroll
        for (int c = 0; c < 4; c++) oa[n2][c] = 0.f;

    for (int kt = 0; kt <= qt; kt++) {
        __syncthreads();
        for (int f = tid; f < 64*16; f += 128) {
            int k = f >> 4, d4 = (f & 15) << 2;
            size_t base = ((size_t)((b*KK + kt*64 + k)*HEADS + h))*HDIM + d4;
            *(float4*)&Ks[k][d4] = *(const float4*)&g_k[base];
            *(float4*)&Vs[k][d4] = *(const float4*)&g_v[base];
        }
        __syncthreads();

        // ---- S = Q K^T (16x64 per warp) ----
        float sc[8][4];
        #pragma unroll
        for (int n2 = 0; n2 < 8; n2++)
            #pragma unroll
            for (int c = 0; c < 4; c++) sc[n2][c] = 0.f;

        #pragma unroll
        for (int ks = 0; ks < 8; ks++) {
            int kb = ks * 8;
            uint32_t a0 = f2tf(Qs[w*16 + gid    ][kb + tid4    ]);
            uint32_t a1 = f2tf(Qs[w*16 + gid + 8][kb + tid4    ]);
            uint32_t a2 = f2tf(Qs[w*16 + gid    ][kb + tid4 + 4]);
            uint32_t a3 = f2tf(Qs[w*16 + gid + 8][kb + tid4 + 4]);
            #pragma unroll
            for (int n2 = 0; n2 < 8; n2++) {
                uint32_t b0 = f2tf(Ks[n2*8 + gid][kb + tid4    ]);
                uint32_t b1 = f2tf(Ks[n2*8 + gid][kb + tid4 + 4]);
                MMA_TF32(sc[n2][0], sc[n2][1], sc[n2][2], sc[n2][3],
                         a0, a1, a2, a3, b0, b1);
            }
        }

        // ---- scale + causal mask + online softmax ----
        bool diag = (kt == qt);
        float mx0 = -1e30f, mx1 = -1e30f;
        #pragma unroll
        for (int n2 = 0; n2 < 8; n2++) {
            int col = kt*64 + n2*8 + 2*tid4;
            sc[n2][0] *= 0.125f; sc[n2][1] *= 0.125f;
            sc[n2][2] *= 0.125f; sc[n2][3] *= 0.125f;
            if (diag) {
                if (col     > r0g) sc[n2][0] = -1e30f;
                if (col + 1 > r0g) sc[n2][1] = -1e30f;
                if (col     > r1g) sc[n2][2] = -1e30f;
                if (col + 1 > r1g) sc[n2][3] = -1e30f;
            }
            mx0 = fmaxf(mx0, fmaxf(sc[n2][0], sc[n2][1]));
            mx1 = fmaxf(mx1, fmaxf(sc[n2][2], sc[n2][3]));
        }
        #pragma unroll
        for (int o = 1; o <= 2; o <<= 1) {
            mx0 = fmaxf(mx0, __shfl_xor_sync(0xffffffffu, mx0, o));
            mx1 = fmaxf(mx1, __shfl_xor_sync(0xffffffffu, mx1, o));
        }
        float mn0 = fmaxf(m0, mx0), mn1 = fmaxf(m1, mx1);
        float cor0 = __expf(m0 - mn0), cor1 = __expf(m1 - mn1);
        m0 = mn0; m1 = mn1;
        float rs0 = 0.f, rs1 = 0.f;
        #pragma unroll
        for (int n2 = 0; n2 < 8; n2++) {
            float p0 = __expf(sc[n2][0] - mn0);
            float p1 = __expf(sc[n2][1] - mn0);
            float p2 = __expf(sc[n2][2] - mn1);
            float p3 = __expf(sc[n2][3] - mn1);
            rs0 += p0 + p1; rs1 += p2 + p3;
            *(float2*)&Ps[w][gid    ][n2*8 + 2*tid4] = make_float2(p0, p1);
            *(float2*)&Ps[w][gid + 8][n2*8 + 2*tid4] = make_float2(p2, p3);
        }
        #pragma unroll
        for (int o = 1; o <= 2; o <<= 1) {
            rs0 += __shfl_xor_sync(0xffffffffu, rs0, o);
            rs1 += __shfl_xor_sync(0xffffffffu, rs1, o);
        }
        l0 = l0 * cor0 + rs0;
        l1 = l1 * cor1 + rs1;
        #pragma unroll
        for (int n2 = 0; n2 < 8; n2++) {
            oa[n2][0] *= cor0; oa[n2][1] *= cor0;
            oa[n2][2] *= cor1; oa[n2][3] *= cor1;
        }
        __syncwarp();

        // ---- O += P V ----
        #pragma unroll
        for (int ks = 0; ks < 8; ks++) {
            uint32_t a0 = f2tf(Ps[w][gid    ][ks*8 + tid4    ]);
            uint32_t a1 = f2tf(Ps[w][gid + 8][ks*8 + tid4    ]);
            uint32_t a2 = f2tf(Ps[w][gid    ][ks*8 + tid4 + 4]);
            uint32_t a3 = f2tf(Ps[w][gid + 8][ks*8 + tid4 + 4]);
            #pragma unroll
            for (int n2 = 0; n2 < 8; n2++) {
                uint32_t b0 = f2tf(Vs[ks*8 + tid4    ][n2*8 + gid]);
                uint32_t b1 = f2tf(Vs[ks*8 + tid4 + 4][n2*8 + gid]);
                MMA_TF32(oa[n2][0], oa[n2][1], oa[n2][2], oa[n2][3],
                         a0, a1, a2, a3, b0, b1);
            }
        }
        __syncwarp();
    }

    float i0 = 1.f / l0, i1 = 1.f / l1;
    #pragma unroll
    for (int n2 = 0; n2 < 8; n2++) {
        int d = n2*8 + 2*tid4;
        *(float2*)&g_o[((size_t)((b*KK + r0g)*HEADS + h))*HDIM + d] =
            make_float2(oa[n2][0]*i0, oa[n2][1]*i0);
        *(float2*)&g_o[((size_t)((b*KK + r1g)*HEADS + h))*HDIM + d] =
            make_float2(oa[n2][2]*i1, oa[n2][3]*i1);
    }
}

// ---------------- silu(gate) * up ------------------------------------------
__global__ void silu_mul_kernel() {
    int i = blockIdx.x * blockDim.x + threadIdx.x;
    const int N4 = BKr*FF/4;
    if (i >= N4) return;
    float4 g = ((const float4*)g_gateb)[i];
    float4 u = ((const float4*)g_upb)[i];
    g.x = g.x / (1.f + __expf(-g.x)) * u.x;
    g.y = g.y / (1.f + __expf(-g.y)) * u.y;
    g.z = g.z / (1.f + __expf(-g.z)) * u.z;
    g.w = g.w / (1.f + __expf(-g.w)) * u.w;
    ((float4*)g_gateb)[i] = g;
}

// ---------------- final gated residual scatter -----------------------------
__global__ void scatter_kernel(float* __restrict__ out) {
    int bj = blockIdx.x;
    int b = bj >> 9;
    int row = g_idx[bj];
    float gate = g_gates[bj];
    float4 xs = ((const float4*)g_xsel)[bj*256 + threadIdx.x];
    float4 bo = ((const float4*)g_bo)[bj*256 + threadIdx.x];
    float4 o;
    o.x = xs.x + gate*(bo.x - xs.x);
    o.y = xs.y + gate*(bo.y - xs.y);
    o.z = xs.z + gate*(bo.z - xs.z);
    o.w = xs.w + gate*(bo.w - xs.w);
    ((float4*)out)[((size_t)(b*TT + row))*256 + threadIdx.x] = o;
}

// ---------------- launch ----------------------------------------------------
extern "C" void kernel_launch(void* const* d_in, const int* in_sizes, int n_in,
                              void* d_out, int out_size) {
    const float* hs  = (const float*)d_in[0];
    const float* wr  = (const float*)d_in[1];
    const float* wq  = (const float*)d_in[2];
    const float* wk  = (const float*)d_in[3];
    const float* wv  = (const float*)d_in[4];
    const float* wo  = (const float*)d_in[5];
    const float* ln1 = (const float*)d_in[6];
    const float* ln2 = (const float*)d_in[7];
    const float* wg  = (const float*)d_in[8];
    const float* wu  = (const float*)d_in[9];
    const float* wd  = (const float*)d_in[10];
    float* out = (float*)d_out;

    float *p_h, *p_xsel, *p_q, *p_k, *p_v, *p_o, *p_x1, *p_h2, *p_gate, *p_up, *p_bo;
    cudaGetSymbolAddress((void**)&p_h,    g_h);
    cudaGetSymbolAddress((void**)&p_xsel, g_xsel);
    cudaGetSymbolAddress((void**)&p_q,    g_q);
    cudaGetSymbolAddress((void**)&p_k,    g_k);
    cudaGetSymbolAddress((void**)&p_v,    g_v);
    cudaGetSymbolAddress((void**)&p_o,    g_o);
    cudaGetSymbolAddress((void**)&p_x1,   g_x1);
    cudaGetSymbolAddress((void**)&p_h2,   g_h2);
    cudaGetSymbolAddress((void**)&p_gate, g_gateb);
    cudaGetSymbolAddress((void**)&p_up,   g_upb);
    cudaGetSymbolAddress((void**)&p_bo,   g_bo);

    cudaMemcpyAsync(out, hs, (size_t)BT*DD*sizeof(float), cudaMemcpyDeviceToDevice);

    router_kernel<<<BT/8, 256>>>(hs, wr);
    topk_kernel<<<BB, 1024>>>();
    aux_kernel<<<1, 1024>>>(out, out_size - 1);
    gather_rms1<<<BKr, 256>>>(hs, ln1);

    // fused QKV (z picks weight/output)
    gemm_tc<<<dim3(DD/128, BKr/128, 3), 256>>>(p_h, wq, wk, wv, nullptr,
                                               p_q, p_k, p_v, BKr, DD, DD);

    rope_kernel<<<(2*BB*KK*HEADS*32 + 255)/256, 256>>>();

    attn_tc<<<dim3(KK/64, HEADS, BB), 128>>>();

    gemm_tc<<<dim3(DD/128, BKr/128, 1), 256>>>(p_o, wo, wo, wo, p_xsel,
                                               p_x1, p_x1, p_x1, BKr, DD, DD);
    rms2_kernel<<<BKr, 256>>>(ln2);

    // fused gate/up
    gemm_tc<<<dim3(FF/128, BKr/128, 2), 256>>>(p_h2, wg, wu, wu, nullptr,
                                               p_gate, p_up, p_up, BKr, FF, DD);
    silu_mul_kernel<<<(BKr*FF/4 + 255)/256, 256>>>();
    gemm_tc<<<dim3(DD/128, BKr/128, 1), 256>>>(p_gate, wd, wd, wd, p_x1,
                                               p_bo, p_bo, p_bo, BKr, DD, FF);

    scatter_kernel<<<BKr, 256>>>(out);
}

// round 5
// speedup vs baseline: 4.2780x; 1.0591x over previous
#include <cuda_runtime.h>
#include <math.h>
#include <stdint.h>

#define BB 4
#define TT 4096
#define DD 1024
#define HEADS 16
#define HDIM 64
#define FF 4096
#define KK 512
#define BT (BB*TT)      // 16384
#define BKr (BB*KK)     // 2048 selected rows total

#define NW1 (DD*DD)     // 1048576
#define NWF (DD*FF)     // 4194304

// ---------------- scratch ----------------------------------------------------
__device__ float g_logits[BT];
__device__ int   g_idx[BKr];
__device__ float g_gates[BKr];
__device__ float g_xsel[BKr*DD];
__device__ float g_h[BKr*DD];
__device__ float g_q[BKr*DD];
__device__ float g_k[BKr*DD];
__device__ float g_v[BKr*DD];
__device__ float g_o[BKr*DD];
__device__ float g_x1[BKr*DD];
__device__ float g_h2[BKr*DD];
__device__ float g_gateb[BKr*FF];
__device__ float g_upb[BKr*FF];
__device__ float g_bo[BKr*DD];
__device__ float g_wbuf[4*NW1 + 3*NWF];   // tf32-rounded weights

// ---------------- helpers ----------------------------------------------------
__device__ __forceinline__ float blk_sum(float v, float* red) {
    int lane = threadIdx.x & 31, w = threadIdx.x >> 5;
    #pragma unroll
    for (int o = 16; o; o >>= 1) v += __shfl_down_sync(0xffffffffu, v, o);
    if (lane == 0) red[w] = v;
    __syncthreads();
    int nw = (blockDim.x + 31) >> 5;
    if (threadIdx.x < 32) {
        float t = (threadIdx.x < nw) ? red[threadIdx.x] : 0.f;
        #pragma unroll
        for (int o = 16; o; o >>= 1) t += __shfl_down_sync(0xffffffffu, t, o);
        if (threadIdx.x == 0) red[0] = t;
    }
    __syncthreads();
    float r = red[0];
    __syncthreads();
    return r;
}

__device__ __forceinline__ uint32_t f2tf(float x) {
    uint32_t y;
    asm("cvt.rna.tf32.f32 %0, %1;" : "=r"(y) : "f"(x));
    return y;
}
__device__ __forceinline__ float rnd(float x) { return __uint_as_float(f2tf(x)); }

__device__ __forceinline__ void cp16(void* s, const void* g) {
    uint32_t sa = (uint32_t)__cvta_generic_to_shared(s);
    asm volatile("cp.async.cg.shared.global [%0], [%1], 16;" :: "r"(sa), "l"(g));
}

#define MMA_TF32(d0,d1,d2,d3,a0,a1,a2,a3,b0,b1) \
    asm volatile("mma.sync.aligned.m16n8k8.row.col.f32.tf32.tf32.f32 " \
        "{%0,%1,%2,%3}, {%4,%5,%6,%7}, {%8,%9}, {%0,%1,%2,%3};" \
        : "+f"(d0), "+f"(d1), "+f"(d2), "+f"(d3) \
        : "r"(a0), "r"(a1), "r"(a2), "r"(a3), "r"(b0), "r"(b1))

// ---------------- weight pre-rounding (tf32 rna) ---------------------------
__global__ void round_kernel(const float* __restrict__ src, float* __restrict__ dst, int n4) {
    int i = blockIdx.x * blockDim.x + threadIdx.x;
    if (i >= n4) return;
    float4 v = ((const float4*)src)[i];
    v.x = rnd(v.x); v.y = rnd(v.y); v.z = rnd(v.z); v.w = rnd(v.w);
    ((float4*)dst)[i] = v;
}

// ---------------- router logits: one warp per token ----------------------
__global__ void router_kernel(const float* __restrict__ hs, const float* __restrict__ wr) {
    int warp = (blockIdx.x * blockDim.x + threadIdx.x) >> 5;
    int lane = threadIdx.x & 31;
    if (warp >= BT) return;
    const float4* row = (const float4*)(hs + (size_t)warp * DD);
    const float4* w   = (const float4*)wr;
    float s = 0.f;
    #pragma unroll
    for (int it = 0; it < 8; it++) {
        float4 a = row[lane + 32 * it];
        float4 b = w[lane + 32 * it];
        s += a.x*b.x + a.y*b.y + a.z*b.z + a.w*b.w;
    }
    #pragma unroll
    for (int o = 16; o; o >>= 1) s += __shfl_down_sync(0xffffffffu, s, o);
    if (lane == 0) g_logits[warp] = s;
}

// ---------------- top-k via full bitonic sort (block per batch) ----------
__global__ void topk_kernel() {
    __shared__ float vals[TT];
    __shared__ int   inds[TT];
    int b = blockIdx.x;
    int tid = threadIdx.x;   // 1024
    for (int i = tid; i < TT; i += 1024) { vals[i] = g_logits[b*TT + i]; inds[i] = i; }
    __syncthreads();
    for (int k = 2; k <= TT; k <<= 1) {
        for (int j = k >> 1; j > 0; j >>= 1) {
            for (int i = tid; i < TT; i += 1024) {
                int ixj = i ^ j;
                if (ixj > i) {
                    float va = vals[i], vb = vals[ixj];
                    int ia = inds[i], ib = inds[ixj];
                    bool a_first = (va > vb) || (va == vb && ia < ib);
                    bool desc = ((i & k) == 0);
                    if (desc ? !a_first : a_first) {
                        vals[i] = vb; vals[ixj] = va;
                        inds[i] = ib; inds[ixj] = ia;
                    }
                }
            }
            __syncthreads();
        }
    }
    for (int k = 2; k <= KK; k <<= 1) {
        for (int j = k >> 1; j > 0; j >>= 1) {
            if (tid < KK) {
                int i = tid, ixj = i ^ j;
                if (ixj > i) {
                    int a = inds[i], c = inds[ixj];
                    bool asc = ((i & k) == 0);
                    if (asc ? (a > c) : (a < c)) { inds[i] = c; inds[ixj] = a; }
                }
            }
            __syncthreads();
        }
    }
    if (tid < KK) {
        int id = inds[tid];
        g_idx[b*KK + tid] = id;
        float l = g_logits[b*TT + id];
        g_gates[b*KK + tid] = 1.f / (1.f + expf(-l));
    }
}

// ---------------- aux loss ------------------------------------------------
__global__ void aux_kernel(float* __restrict__ out, int aux_off) {
    __shared__ float red[32];
    float s = 0.f;
    for (int i = threadIdx.x; i < BT; i += blockDim.x) {
        float l = g_logits[i];
        s += fmaxf(l, 0.f) + log1pf(expf(-fabsf(l)));
    }
    for (int i = threadIdx.x; i < BKr; i += blockDim.x) {
        int b = i >> 9;
        s -= g_logits[b*TT + g_idx[i]];
    }
    float tot = blk_sum(s, red);
    if (threadIdx.x == 0) out[aux_off] = tot * (0.01f / (float)BT);
}

// ---------------- gather + rmsnorm1 (h output tf32-rounded) ----------------
__global__ void gather_rms1(const float* __restrict__ hs, const float* __restrict__ ln1) {
    __shared__ float red[32];
    int bj = blockIdx.x;
    int b = bj >> 9;
    int row = g_idx[bj];
    const float4* src = (const float4*)(hs + ((size_t)(b*TT + row)) * DD);
    float4 x = src[threadIdx.x];
    float ss = x.x*x.x + x.y*x.y + x.z*x.z + x.w*x.w;
    float tot = blk_sum(ss, red);
    float r = rsqrtf(tot / (float)DD + 1e-6f);
    ((float4*)g_xsel)[bj*256 + threadIdx.x] = x;
    float4 w = ((const float4*)ln1)[threadIdx.x];
    float4 hv = make_float4(rnd(x.x*r*w.x), rnd(x.y*r*w.y), rnd(x.z*r*w.z), rnd(x.w*r*w.w));
    ((float4*)g_h)[bj*256 + threadIdx.x] = hv;
}

// ---------------- rmsnorm2 (h2 output tf32-rounded) -------------------------
__global__ void rms2_kernel(const float* __restrict__ ln2) {
    __shared__ float red[32];
    int bj = blockIdx.x;
    float4 x = ((const float4*)g_x1)[bj*256 + threadIdx.x];
    float ss = x.x*x.x + x.y*x.y + x.z*x.z + x.w*x.w;
    float tot = blk_sum(ss, red);
    float r = rsqrtf(tot / (float)DD + 1e-6f);
    float4 w = ((const float4*)ln2)[threadIdx.x];
    float4 hv = make_float4(rnd(x.x*r*w.x), rnd(x.y*r*w.y), rnd(x.z*r*w.z), rnd(x.w*r*w.w));
    ((float4*)g_h2)[bj*256 + threadIdx.x] = hv;
}

// ---------------- TF32 tensor-core GEMM with cp.async ----------------------
// Inputs MUST be pre-rounded to tf32 (rna). No cvt in the hot loop.
// C_z = A @ B_z (+res). round_out: round outputs to tf32 (for v path).
#define ASTR 36
#define BSTR 136
__global__ __launch_bounds__(256) void gemm_tc(
    const float* __restrict__ A,
    const float* __restrict__ B0, const float* __restrict__ B1, const float* __restrict__ B2,
    const float* __restrict__ res,
    float* __restrict__ C0, float* __restrict__ C1, float* __restrict__ C2,
    int M, int N, int K, int round_out)
{
    const float* B = (blockIdx.z == 0) ? B0 : (blockIdx.z == 1 ? B1 : B2);
    float*       C = (blockIdx.z == 0) ? C0 : (blockIdx.z == 1 ? C1 : C2);

    __shared__ float As[2][128][ASTR];
    __shared__ float Bs[2][32][BSTR];
    int tid = threadIdx.x;
    int w = tid >> 5, lane = tid & 31;
    int wm = w >> 1, wn = w & 1;
    int gid = lane >> 2, tid4 = lane & 3;
    int row0 = blockIdx.y * 128, col0 = blockIdx.x * 128;

    int arr = tid >> 3;
    int arc = (tid & 7) * 4;
    int brk = tid >> 5;
    int brc = (tid & 31) * 4;

    float acc[2][8][4];
    #pragma unroll
    for (int i = 0; i < 2; i++)
        #pragma unroll
        for (int j = 0; j < 8; j++)
            #pragma unroll
            for (int c = 0; c < 4; c++) acc[i][j][c] = 0.f;

    int nt = K / 32;

    #pragma unroll
    for (int p = 0; p < 4; p++)
        cp16(&As[0][arr + p*32][arc], &A[(size_t)(row0 + arr + p*32)*K + arc]);
    #pragma unroll
    for (int p = 0; p < 4; p++)
        cp16(&Bs[0][brk + p*8][brc], &B[(size_t)(brk + p*8)*N + col0 + brc]);
    asm volatile("cp.async.commit_group;");

    int buf = 0;
    for (int t = 0; t < nt; t++) {
        if (t + 1 < nt) {
            int k0 = (t + 1) * 32;
            #pragma unroll
            for (int p = 0; p < 4; p++)
                cp16(&As[buf^1][arr + p*32][arc], &A[(size_t)(row0 + arr + p*32)*K + k0 + arc]);
            #pragma unroll
            for (int p = 0; p < 4; p++)
                cp16(&Bs[buf^1][brk + p*8][brc], &B[(size_t)(k0 + brk + p*8)*N + col0 + brc]);
            asm volatile("cp.async.commit_group;");
            asm volatile("cp.async.wait_group 1;");
        } else {
            asm volatile("cp.async.wait_group 0;");
        }
        __syncthreads();

        const uint32_t* Au = (const uint32_t*)&As[buf][0][0];
        const uint32_t* Bu = (const uint32_t*)&Bs[buf][0][0];
        #pragma unroll
        for (int ks = 0; ks < 4; ks++) {
            int kb = ks * 8;
            uint32_t af[2][4];
            #pragma unroll
            for (int mt = 0; mt < 2; mt++) {
                int rm = wm*32 + mt*16;
                af[mt][0] = Au[(rm + gid    )*ASTR + kb + tid4    ];
                af[mt][1] = Au[(rm + gid + 8)*ASTR + kb + tid4    ];
                af[mt][2] = Au[(rm + gid    )*ASTR + kb + tid4 + 4];
                af[mt][3] = Au[(rm + gid + 8)*ASTR + kb + tid4 + 4];
            }
            #pragma unroll
            for (int n2 = 0; n2 < 8; n2++) {
                int cn = wn*64 + n2*8 + gid;
                uint32_t b0 = Bu[(kb + tid4    )*BSTR + cn];
                uint32_t b1 = Bu[(kb + tid4 + 4)*BSTR + cn];
                MMA_TF32(acc[0][n2][0], acc[0][n2][1], acc[0][n2][2], acc[0][n2][3],
                         af[0][0], af[0][1], af[0][2], af[0][3], b0, b1);
                MMA_TF32(acc[1][n2][0], acc[1][n2][1], acc[1][n2][2], acc[1][n2][3],
                         af[1][0], af[1][1], af[1][2], af[1][3], b0, b1);
            }
        }
        __syncthreads();
        buf ^= 1;
    }

    #pragma unroll
    for (int mt = 0; mt < 2; mt++) {
        int row = row0 + wm*32 + mt*16 + gid;
        #pragma unroll
        for (int n2 = 0; n2 < 8; n2++) {
            int col = col0 + wn*64 + n2*8 + tid4*2;
            float2 v0 = make_float2(acc[mt][n2][0], acc[mt][n2][1]);
            float2 v1 = make_float2(acc[mt][n2][2], acc[mt][n2][3]);
            if (res) {
                float2 r0 = *(const float2*)&res[(size_t)row*N + col];
                float2 r1 = *(const float2*)&res[(size_t)(row+8)*N + col];
                v0.x += r0.x; v0.y += r0.y;
                v1.x += r1.x; v1.y += r1.y;
            }
            if (round_out) {
                v0.x = rnd(v0.x); v0.y = rnd(v0.y);
                v1.x = rnd(v1.x); v1.y = rnd(v1.y);
            }
            *(float2*)&C[(size_t)row*N + col]     = v0;
            *(float2*)&C[(size_t)(row+8)*N + col] = v1;
        }
    }
}

// ---------------- RoPE on q and k (in place, rounded output) --------------
__global__ void rope_kernel() {
    int i = blockIdx.x * blockDim.x + threadIdx.x;
    const int NPAIR = BB*KK*HEADS*32;
    if (i >= 2*NPAIR) return;
    int which = (i >= NPAIR);
    int r = which ? (i - NPAIR) : i;
    int d  = r & 31;
    int hh = (r >> 5) & 15;
    int j  = (r >> 9) & (KK-1);
    int b  = r >> (9 + 9);
    float* base = which ? g_k : g_q;
    int off = ((b*KK + j)*HEADS + hh)*HDIM;
    float inv = expf(-logf(10000.f) * (float)d / 32.f);
    float pos = (float)g_idx[b*KK + j];
    float ang = pos * inv;
    float c = cosf(ang), s = sinf(ang);
    float x1 = base[off + d];
    float x2 = base[off + d + 32];
    base[off + d]      = rnd(x1*c - x2*s);
    base[off + d + 32] = rnd(x2*c + x1*s);
}

// ---------------- tensor-core flash attention ------------------------------
// Q/K/V pre-rounded; only P needs cvt. Output g_o rounded (feeds wo GEMM).
__global__ __launch_bounds__(128) void attn_tc() {
    __shared__ float Qs[64][68];
    __shared__ float Ks[64][68];
    __shared__ float Vs[64][72];
    __shared__ float Ps[4][16][68];
    int qt = blockIdx.x, h = blockIdx.y, b = blockIdx.z;
    int tid = threadIdx.x, w = tid >> 5, lane = tid & 31;
    int gid = lane >> 2, tid4 = lane & 3;

    for (int f = tid; f < 64*16; f += 128) {
        int q = f >> 4, d4 = (f & 15) << 2;
        *(float4*)&Qs[q][d4] =
            *(const float4*)&g_q[((size_t)((b*KK + qt*64 + q)*HEADS + h))*HDIM + d4];
    }

    int r0g = qt*64 + w*16 + gid;
    int r1g = r0g + 8;

    float m0 = -1e30f, m1 = -1e30f, l0 = 0.f, l1 = 0.f;
    float oa[8][4];
    #pragma unroll
    for (int n2 = 0; n2 < 8; n2++)
        #pragma unroll
        for (int c = 0; c < 4; c++) oa[n2][c] = 0.f;

    for (int kt = 0; kt <= qt; kt++) {
        __syncthreads();
        for (int f = tid; f < 64*16; f += 128) {
            int k = f >> 4, d4 = (f & 15) << 2;
            size_t base = ((size_t)((b*KK + kt*64 + k)*HEADS + h))*HDIM + d4;
            *(float4*)&Ks[k][d4] = *(const float4*)&g_k[base];
            *(float4*)&Vs[k][d4] = *(const float4*)&g_v[base];
        }
        __syncthreads();

        float sc[8][4];
        #pragma unroll
        for (int n2 = 0; n2 < 8; n2++)
            #pragma unroll
            for (int c = 0; c < 4; c++) sc[n2][c] = 0.f;

        #pragma unroll
        for (int ks = 0; ks < 8; ks++) {
            int kb = ks * 8;
            uint32_t a0 = __float_as_uint(Qs[w*16 + gid    ][kb + tid4    ]);
            uint32_t a1 = __float_as_uint(Qs[w*16 + gid + 8][kb + tid4    ]);
            uint32_t a2 = __float_as_uint(Qs[w*16 + gid    ][kb + tid4 + 4]);
            uint32_t a3 = __float_as_uint(Qs[w*16 + gid + 8][kb + tid4 + 4]);
            #pragma unroll
            for (int n2 = 0; n2 < 8; n2++) {
                uint32_t b0 = __float_as_uint(Ks[n2*8 + gid][kb + tid4    ]);
                uint32_t b1 = __float_as_uint(Ks[n2*8 + gid][kb + tid4 + 4]);
                MMA_TF32(sc[n2][0], sc[n2][1], sc[n2][2], sc[n2][3],
                         a0, a1, a2, a3, b0, b1);
            }
        }

        bool diag = (kt == qt);
        float mx0 = -1e30f, mx1 = -1e30f;
        #pragma unroll
        for (int n2 = 0; n2 < 8; n2++) {
            int col = kt*64 + n2*8 + 2*tid4;
            sc[n2][0] *= 0.125f; sc[n2][1] *= 0.125f;
            sc[n2][2] *= 0.125f; sc[n2][3] *= 0.125f;
            if (diag) {
                if (col     > r0g) sc[n2][0] = -1e30f;
                if (col + 1 > r0g) sc[n2][1] = -1e30f;
                if (col     > r1g) sc[n2][2] = -1e30f;
                if (col + 1 > r1g) sc[n2][3] = -1e30f;
            }
            mx0 = fmaxf(mx0, fmaxf(sc[n2][0], sc[n2][1]));
            mx1 = fmaxf(mx1, fmaxf(sc[n2][2], sc[n2][3]));
        }
        #pragma unroll
        for (int o = 1; o <= 2; o <<= 1) {
            mx0 = fmaxf(mx0, __shfl_xor_sync(0xffffffffu, mx0, o));
            mx1 = fmaxf(mx1, __shfl_xor_sync(0xffffffffu, mx1, o));
        }
        float mn0 = fmaxf(m0, mx0), mn1 = fmaxf(m1, mx1);
        float cor0 = __expf(m0 - mn0), cor1 = __expf(m1 - mn1);
        m0 = mn0; m1 = mn1;
        float rs0 = 0.f, rs1 = 0.f;
        #pragma unroll
        for (int n2 = 0; n2 < 8; n2++) {
            float p0 = __expf(sc[n2][0] - mn0);
            float p1 = __expf(sc[n2][1] - mn0);
            float p2 = __expf(sc[n2][2] - mn1);
            float p3 = __expf(sc[n2][3] - mn1);
            rs0 += p0 + p1; rs1 += p2 + p3;
            *(float2*)&Ps[w][gid    ][n2*8 + 2*tid4] = make_float2(rnd(p0), rnd(p1));
            *(float2*)&Ps[w][gid + 8][n2*8 + 2*tid4] = make_float2(rnd(p2), rnd(p3));
        }
        #pragma unroll
        for (int o = 1; o <= 2; o <<= 1) {
            rs0 += __shfl_xor_sync(0xffffffffu, rs0, o);
            rs1 += __shfl_xor_sync(0xffffffffu, rs1, o);
        }
        l0 = l0 * cor0 + rs0;
        l1 = l1 * cor1 + rs1;
        #pragma unroll
        for (int n2 = 0; n2 < 8; n2++) {
            oa[n2][0] *= cor0; oa[n2][1] *= cor0;
            oa[n2][2] *= cor1; oa[n2][3] *= cor1;
        }
        __syncwarp();

        #pragma unroll
        for (int ks = 0; ks < 8; ks++) {
            uint32_t a0 = __float_as_uint(Ps[w][gid    ][ks*8 + tid4    ]);
            uint32_t a1 = __float_as_uint(Ps[w][gid + 8][ks*8 + tid4    ]);
            uint32_t a2 = __float_as_uint(Ps[w][gid    ][ks*8 + tid4 + 4]);
            uint32_t a3 = __float_as_uint(Ps[w][gid + 8][ks*8 + tid4 + 4]);
            #pragma unroll
            for (int n2 = 0; n2 < 8; n2++) {
                uint32_t b0 = __float_as_uint(Vs[ks*8 + tid4    ][n2*8 + gid]);
                uint32_t b1 = __float_as_uint(Vs[ks*8 + tid4 + 4][n2*8 + gid]);
                MMA_TF32(oa[n2][0], oa[n2][1], oa[n2][2], oa[n2][3],
                         a0, a1, a2, a3, b0, b1);
            }
        }
        __syncwarp();
    }

    float i0 = 1.f / l0, i1 = 1.f / l1;
    #pragma unroll
    for (int n2 = 0; n2 < 8; n2++) {
        int d = n2*8 + 2*tid4;
        *(float2*)&g_o[((size_t)((b*KK + r0g)*HEADS + h))*HDIM + d] =
            make_float2(rnd(oa[n2][0]*i0), rnd(oa[n2][1]*i0));
        *(float2*)&g_o[((size_t)((b*KK + r1g)*HEADS + h))*HDIM + d] =
            make_float2(rnd(oa[n2][2]*i1), rnd(oa[n2][3]*i1));
    }
}

// ---------------- silu(gate) * up (rounded output, feeds down GEMM) --------
__global__ void silu_mul_kernel() {
    int i = blockIdx.x * blockDim.x + threadIdx.x;
    const int N4 = BKr*FF/4;
    if (i >= N4) return;
    float4 g = ((const float4*)g_gateb)[i];
    float4 u = ((const float4*)g_upb)[i];
    g.x = rnd(g.x / (1.f + __expf(-g.x)) * u.x);
    g.y = rnd(g.y / (1.f + __expf(-g.y)) * u.y);
    g.z = rnd(g.z / (1.f + __expf(-g.z)) * u.z);
    g.w = rnd(g.w / (1.f + __expf(-g.w)) * u.w);
    ((float4*)g_gateb)[i] = g;
}

// ---------------- final gated residual scatter -----------------------------
__global__ void scatter_kernel(float* __restrict__ out) {
    int bj = blockIdx.x;
    int b = bj >> 9;
    int row = g_idx[bj];
    float gate = g_gates[bj];
    float4 xs = ((const float4*)g_xsel)[bj*256 + threadIdx.x];
    float4 bo = ((const float4*)g_bo)[bj*256 + threadIdx.x];
    float4 o;
    o.x = xs.x + gate*(bo.x - xs.x);
    o.y = xs.y + gate*(bo.y - xs.y);
    o.z = xs.z + gate*(bo.z - xs.z);
    o.w = xs.w + gate*(bo.w - xs.w);
    ((float4*)out)[((size_t)(b*TT + row))*256 + threadIdx.x] = o;
}

// ---------------- launch ----------------------------------------------------
extern "C" void kernel_launch(void* const* d_in, const int* in_sizes, int n_in,
                              void* d_out, int out_size) {
    const float* hs  = (const float*)d_in[0];
    const float* wr  = (const float*)d_in[1];
    const float* wq  = (const float*)d_in[2];
    const float* wk  = (const float*)d_in[3];
    const float* wv  = (const float*)d_in[4];
    const float* wo  = (const float*)d_in[5];
    const float* ln1 = (const float*)d_in[6];
    const float* ln2 = (const float*)d_in[7];
    const float* wg  = (const float*)d_in[8];
    const float* wu  = (const float*)d_in[9];
    const float* wd  = (const float*)d_in[10];
    float* out = (float*)d_out;

    float *p_h, *p_xsel, *p_q, *p_k, *p_v, *p_o, *p_x1, *p_h2, *p_gate, *p_up, *p_bo, *p_wb;
    cudaGetSymbolAddress((void**)&p_h,    g_h);
    cudaGetSymbolAddress((void**)&p_xsel, g_xsel);
    cudaGetSymbolAddress((void**)&p_q,    g_q);
    cudaGetSymbolAddress((void**)&p_k,    g_k);
    cudaGetSymbolAddress((void**)&p_v,    g_v);
    cudaGetSymbolAddress((void**)&p_o,    g_o);
    cudaGetSymbolAddress((void**)&p_x1,   g_x1);
    cudaGetSymbolAddress((void**)&p_h2,   g_h2);
    cudaGetSymbolAddress((void**)&p_gate, g_gateb);
    cudaGetSymbolAddress((void**)&p_up,   g_upb);
    cudaGetSymbolAddress((void**)&p_bo,   g_bo);
    cudaGetSymbolAddress((void**)&p_wb,   g_wbuf);

    float* rwq = p_wb;
    float* rwk = p_wb + NW1;
    float* rwv = p_wb + 2*NW1;
    float* rwo = p_wb + 3*NW1;
    float* rwg = p_wb + 4*NW1;
    float* rwu = p_wb + 4*NW1 + NWF;
    float* rwd = p_wb + 4*NW1 + 2*NWF;

    cudaMemcpyAsync(out, hs, (size_t)BT*DD*sizeof(float), cudaMemcpyDeviceToDevice);

    // pre-round weights to tf32 (rna) — removes all cvts from GEMM hot loops
    round_kernel<<<NW1/4/256, 256>>>(wq, rwq, NW1/4);
    round_kernel<<<NW1/4/256, 256>>>(wk, rwk, NW1/4);
    round_kernel<<<NW1/4/256, 256>>>(wv, rwv, NW1/4);
    round_kernel<<<NW1/4/256, 256>>>(wo, rwo, NW1/4);
    round_kernel<<<NWF/4/256, 256>>>(wg, rwg, NWF/4);
    round_kernel<<<NWF/4/256, 256>>>(wu, rwu, NWF/4);
    round_kernel<<<NWF/4/256, 256>>>(wd, rwd, NWF/4);

    router_kernel<<<BT/8, 256>>>(hs, wr);
    topk_kernel<<<BB, 1024>>>();
    aux_kernel<<<1, 1024>>>(out, out_size - 1);
    gather_rms1<<<BKr, 256>>>(hs, ln1);

    // fused QKV; round outputs (v consumed directly, q/k re-rounded by rope)
    gemm_tc<<<dim3(DD/128, BKr/128, 3), 256>>>(p_h, rwq, rwk, rwv, nullptr,
                                               p_q, p_k, p_v, BKr, DD, DD, 1);

    rope_kernel<<<(2*BB*KK*HEADS*32 + 255)/256, 256>>>();

    attn_tc<<<dim3(KK/64, HEADS, BB), 128>>>();

    gemm_tc<<<dim3(DD/128, BKr/128, 1), 256>>>(p_o, rwo, rwo, rwo, p_xsel,
                                               p_x1, p_x1, p_x1, BKr, DD, DD, 0);
    rms2_kernel<<<BKr, 256>>>(ln2);

    gemm_tc<<<dim3(FF/128, BKr/128, 2), 256>>>(p_h2, rwg, rwu, rwu, nullptr,
                                               p_gate, p_up, p_up, BKr, FF, DD, 0);
    silu_mul_kernel<<<(BKr*FF/4 + 255)/256, 256>>>();
    gemm_tc<<<dim3(DD/128, BKr/128, 1), 256>>>(p_gate, rwd, rwd, rwd, p_x1,
                                               p_bo, p_bo, p_bo, BKr, DD, FF, 0);

    scatter_kernel<<<BKr, 256>>>(out);
}

// round 6
// speedup vs baseline: 5.7579x; 1.3459x over previous
#include <cuda_runtime.h>
#include <cuda_bf16.h>
#include <math.h>
#include <stdint.h>

#define BB 4
#define TT 4096
#define DD 1024
#define HEADS 16
#define HDIM 64
#define FF 4096
#define KK 512
#define BT (BB*TT)      // 16384
#define BKr (BB*KK)     // 2048

#define NW1 (DD*DD)
#define NWF (DD*FF)

// ---------------- scratch ----------------------------------------------------
__device__ float g_logits[BT];
__device__ int   g_idx[BKr];
__device__ float g_gates[BKr];
__device__ float g_xsel[BKr*DD];
__device__ float g_q[BKr*DD];
__device__ float g_k[BKr*DD];
__device__ float g_v[BKr*DD];
__device__ float g_x1[BKr*DD];
__device__ float g_gateb[BKr*FF];
__device__ float g_upb[BKr*FF];
__device__ float g_bo[BKr*DD];
__device__ __nv_bfloat16 g_hb[BKr*DD];     // rmsnorm1 out (A of QKV)
__device__ __nv_bfloat16 g_ob[BKr*DD];     // attn out (A of WO)
__device__ __nv_bfloat16 g_h2b[BKr*DD];    // rmsnorm2 out (A of gate/up)
__device__ __nv_bfloat16 g_mlpa[BKr*FF];   // silu*up (A of down)
__device__ uint32_t g_wpack[(4*NW1 + 3*NWF)/2];   // bf16 k-pair packed weights

// ---------------- helpers ----------------------------------------------------
__device__ __forceinline__ float blk_sum(float v, float* red) {
    int lane = threadIdx.x & 31, w = threadIdx.x >> 5;
    #pragma unroll
    for (int o = 16; o; o >>= 1) v += __shfl_down_sync(0xffffffffu, v, o);
    if (lane == 0) red[w] = v;
    __syncthreads();
    int nw = (blockDim.x + 31) >> 5;
    if (threadIdx.x < 32) {
        float t = (threadIdx.x < nw) ? red[threadIdx.x] : 0.f;
        #pragma unroll
        for (int o = 16; o; o >>= 1) t += __shfl_down_sync(0xffffffffu, t, o);
        if (threadIdx.x == 0) red[0] = t;
    }
    __syncthreads();
    float r = red[0];
    __syncthreads();
    return r;
}

__device__ __forceinline__ uint32_t f2tf(float x) {
    uint32_t y;
    asm("cvt.rna.tf32.f32 %0, %1;" : "=r"(y) : "f"(x));
    return y;
}
__device__ __forceinline__ float rnd(float x) { return __uint_as_float(f2tf(x)); }

__device__ __forceinline__ uint32_t pack_bf2(float lo, float hi) {
    __nv_bfloat162 t = __floats2bfloat162_rn(lo, hi);
    return *(uint32_t*)&t;
}

__device__ __forceinline__ void cp16(void* s, const void* g) {
    uint32_t sa = (uint32_t)__cvta_generic_to_shared(s);
    asm volatile("cp.async.cg.shared.global [%0], [%1], 16;" :: "r"(sa), "l"(g));
}

#define MMA_BF16(d0,d1,d2,d3,a0,a1,a2,a3,b0,b1) \
    asm volatile("mma.sync.aligned.m16n8k16.row.col.f32.bf16.bf16.f32 " \
        "{%0,%1,%2,%3}, {%4,%5,%6,%7}, {%8,%9}, {%0,%1,%2,%3};" \
        : "+f"(d0), "+f"(d1), "+f"(d2), "+f"(d3) \
        : "r"(a0), "r"(a1), "r"(a2), "r"(a3), "r"(b0), "r"(b1))

#define MMA_TF32(d0,d1,d2,d3,a0,a1,a2,a3,b0,b1) \
    asm volatile("mma.sync.aligned.m16n8k8.row.col.f32.tf32.tf32.f32 " \
        "{%0,%1,%2,%3}, {%4,%5,%6,%7}, {%8,%9}, {%0,%1,%2,%3};" \
        : "+f"(d0), "+f"(d1), "+f"(d2), "+f"(d3) \
        : "r"(a0), "r"(a1), "r"(a2), "r"(a3), "r"(b0), "r"(b1))

// ---------------- weight pack: fp32 [K][N] -> bf16 pair u32 [K/2][N] --------
__global__ void pack_kernel(const float* __restrict__ src, uint32_t* __restrict__ dst,
                            int N, int n4) {
    int i = blockIdx.x * blockDim.x + threadIdx.x;
    if (i >= n4) return;
    int flat = i * 4;
    int k2 = flat / N;
    int n0 = flat - k2 * N;
    const float4 r0 = *(const float4*)&src[(size_t)(2*k2    )*N + n0];
    const float4 r1 = *(const float4*)&src[(size_t)(2*k2 + 1)*N + n0];
    uint4 o;
    o.x = pack_bf2(r0.x, r1.x);
    o.y = pack_bf2(r0.y, r1.y);
    o.z = pack_bf2(r0.z, r1.z);
    o.w = pack_bf2(r0.w, r1.w);
    *(uint4*)&dst[(size_t)k2*N + n0] = o;
}

// ---------------- router logits --------------------------------------------
__global__ void router_kernel(const float* __restrict__ hs, const float* __restrict__ wr) {
    int warp = (blockIdx.x * blockDim.x + threadIdx.x) >> 5;
    int lane = threadIdx.x & 31;
    if (warp >= BT) return;
    const float4* row = (const float4*)(hs + (size_t)warp * DD);
    const float4* w   = (const float4*)wr;
    float s = 0.f;
    #pragma unroll
    for (int it = 0; it < 8; it++) {
        float4 a = row[lane + 32 * it];
        float4 b = w[lane + 32 * it];
        s += a.x*b.x + a.y*b.y + a.z*b.z + a.w*b.w;
    }
    #pragma unroll
    for (int o = 16; o; o >>= 1) s += __shfl_down_sync(0xffffffffu, s, o);
    if (lane == 0) g_logits[warp] = s;
}

// ---------------- top-k (block per batch) -----------------------------------
__global__ void topk_kernel() {
    __shared__ float vals[TT];
    __shared__ int   inds[TT];
    int b = blockIdx.x;
    int tid = threadIdx.x;
    for (int i = tid; i < TT; i += 1024) { vals[i] = g_logits[b*TT + i]; inds[i] = i; }
    __syncthreads();
    for (int k = 2; k <= TT; k <<= 1) {
        for (int j = k >> 1; j > 0; j >>= 1) {
            for (int i = tid; i < TT; i += 1024) {
                int ixj = i ^ j;
                if (ixj > i) {
                    float va = vals[i], vb = vals[ixj];
                    int ia = inds[i], ib = inds[ixj];
                    bool a_first = (va > vb) || (va == vb && ia < ib);
                    bool desc = ((i & k) == 0);
                    if (desc ? !a_first : a_first) {
                        vals[i] = vb; vals[ixj] = va;
                        inds[i] = ib; inds[ixj] = ia;
                    }
                }
            }
            __syncthreads();
        }
    }
    for (int k = 2; k <= KK; k <<= 1) {
        for (int j = k >> 1; j > 0; j >>= 1) {
            if (tid < KK) {
                int i = tid, ixj = i ^ j;
                if (ixj > i) {
                    int a = inds[i], c = inds[ixj];
                    bool asc = ((i & k) == 0);
                    if (asc ? (a > c) : (a < c)) { inds[i] = c; inds[ixj] = a; }
                }
            }
            __syncthreads();
        }
    }
    if (tid < KK) {
        int id = inds[tid];
        g_idx[b*KK + tid] = id;
        float l = g_logits[b*TT + id];
        g_gates[b*KK + tid] = 1.f / (1.f + expf(-l));
    }
}

// ---------------- aux loss ---------------------------------------------------
__global__ void aux_kernel(float* __restrict__ out, int aux_off) {
    __shared__ float red[32];
    float s = 0.f;
    for (int i = threadIdx.x; i < BT; i += blockDim.x) {
        float l = g_logits[i];
        s += fmaxf(l, 0.f) + log1pf(expf(-fabsf(l)));
    }
    for (int i = threadIdx.x; i < BKr; i += blockDim.x) {
        int b = i >> 9;
        s -= g_logits[b*TT + g_idx[i]];
    }
    float tot = blk_sum(s, red);
    if (threadIdx.x == 0) out[aux_off] = tot * (0.01f / (float)BT);
}

// ---------------- gather + rmsnorm1 -> bf16 ---------------------------------
__global__ void gather_rms1(const float* __restrict__ hs, const float* __restrict__ ln1) {
    __shared__ float red[32];
    int bj = blockIdx.x;
    int b = bj >> 9;
    int row = g_idx[bj];
    const float4* src = (const float4*)(hs + ((size_t)(b*TT + row)) * DD);
    float4 x = src[threadIdx.x];
    float ss = x.x*x.x + x.y*x.y + x.z*x.z + x.w*x.w;
    float tot = blk_sum(ss, red);
    float r = rsqrtf(tot / (float)DD + 1e-6f);
    ((float4*)g_xsel)[bj*256 + threadIdx.x] = x;
    float4 w = ((const float4*)ln1)[threadIdx.x];
    uint32_t lo = pack_bf2(x.x*r*w.x, x.y*r*w.y);
    uint32_t hi = pack_bf2(x.z*r*w.z, x.w*r*w.w);
    *(uint2*)&g_hb[(size_t)bj*DD + threadIdx.x*4] = make_uint2(lo, hi);
}

// ---------------- rmsnorm2 -> bf16 -------------------------------------------
__global__ void rms2_kernel(const float* __restrict__ ln2) {
    __shared__ float red[32];
    int bj = blockIdx.x;
    float4 x = ((const float4*)g_x1)[bj*256 + threadIdx.x];
    float ss = x.x*x.x + x.y*x.y + x.z*x.z + x.w*x.w;
    float tot = blk_sum(ss, red);
    float r = rsqrtf(tot / (float)DD + 1e-6f);
    float4 w = ((const float4*)ln2)[threadIdx.x];
    uint32_t lo = pack_bf2(x.x*r*w.x, x.y*r*w.y);
    uint32_t hi = pack_bf2(x.z*r*w.z, x.w*r*w.w);
    *(uint2*)&g_h2b[(size_t)bj*DD + threadIdx.x*4] = make_uint2(lo, hi);
}

// ---------------- BF16 tensor-core GEMM --------------------------------------
// A: bf16 [M,K] row-major. B: packed u32 [K/2][N] (u32 = {B[2k][n],B[2k+1][n]}).
// C: fp32 [M,N] (+res). 128x128 CTA tile, K-slice 32, double-buffered cp.async.
#define ASTR 20     // u32 stride (16 data + 4 pad)
#define BSTR 136    // u32 stride (128 data + 8 pad)
__global__ __launch_bounds__(256) void gemm_bf(
    const __nv_bfloat16* __restrict__ A,
    const uint32_t* __restrict__ B0, const uint32_t* __restrict__ B1, const uint32_t* __restrict__ B2,
    const float* __restrict__ res,
    float* __restrict__ C0, float* __restrict__ C1, float* __restrict__ C2,
    int M, int N, int K, int round_out)
{
    const uint32_t* B = (blockIdx.z == 0) ? B0 : (blockIdx.z == 1 ? B1 : B2);
    float*          C = (blockIdx.z == 0) ? C0 : (blockIdx.z == 1 ? C1 : C2);

    __shared__ uint32_t As[2][128][ASTR];
    __shared__ uint32_t Bs[2][16][BSTR];
    int tid = threadIdx.x;
    int w = tid >> 5, lane = tid & 31;
    int wm = w >> 1, wn = w & 1;
    int gid = lane >> 2, tid4 = lane & 3;
    int row0 = blockIdx.y * 128, col0 = blockIdx.x * 128;

    const uint32_t* Au = (const uint32_t*)A;
    int K2 = K >> 1;                 // u32 per A row

    int arr = tid >> 1;              // 0..127
    int arc = (tid & 1) * 8;         // 0 or 8 (u32 col); copies 4 u32 at arc, arc+4
    int brw = tid >> 4;              // 0..15
    int bcc = (tid & 15) * 4;        // 0..60; copies at bcc, bcc+64

    float acc[2][8][4];
    #pragma unroll
    for (int i = 0; i < 2; i++)
        #pragma unroll
        for (int j = 0; j < 8; j++)
            #pragma unroll
            for (int c = 0; c < 4; c++) acc[i][j][c] = 0.f;

    int nt = K / 32;

    cp16(&As[0][arr][arc],     &Au[(size_t)(row0 + arr)*K2 + arc]);
    cp16(&As[0][arr][arc + 4], &Au[(size_t)(row0 + arr)*K2 + arc + 4]);
    cp16(&Bs[0][brw][bcc],      &B[(size_t)brw*N + col0 + bcc]);
    cp16(&Bs[0][brw][bcc + 64], &B[(size_t)brw*N + col0 + bcc + 64]);
    asm volatile("cp.async.commit_group;");

    int buf = 0;
    for (int t = 0; t < nt; t++) {
        if (t + 1 < nt) {
            int k2o = (t + 1) * 16;
            cp16(&As[buf^1][arr][arc],     &Au[(size_t)(row0 + arr)*K2 + k2o + arc]);
            cp16(&As[buf^1][arr][arc + 4], &Au[(size_t)(row0 + arr)*K2 + k2o + arc + 4]);
            cp16(&Bs[buf^1][brw][bcc],      &B[(size_t)(k2o + brw)*N + col0 + bcc]);
            cp16(&Bs[buf^1][brw][bcc + 64], &B[(size_t)(k2o + brw)*N + col0 + bcc + 64]);
            asm volatile("cp.async.commit_group;");
            asm volatile("cp.async.wait_group 1;");
        } else {
            asm volatile("cp.async.wait_group 0;");
        }
        __syncthreads();

        #pragma unroll
        for (int ks = 0; ks < 2; ks++) {
            int kb = ks * 8;
            uint32_t af[2][4];
            #pragma unroll
            for (int mt = 0; mt < 2; mt++) {
                int rm = wm*32 + mt*16;
                af[mt][0] = As[buf][rm + gid    ][kb + tid4    ];
                af[mt][1] = As[buf][rm + gid + 8][kb + tid4    ];
                af[mt][2] = As[buf][rm + gid    ][kb + tid4 + 4];
                af[mt][3] = As[buf][rm + gid + 8][kb + tid4 + 4];
            }
            #pragma unroll
            for (int n2 = 0; n2 < 8; n2++) {
                int cn = wn*64 + n2*8 + gid;
                uint32_t b0 = Bs[buf][kb + tid4    ][cn];
                uint32_t b1 = Bs[buf][kb + tid4 + 4][cn];
                MMA_BF16(acc[0][n2][0], acc[0][n2][1], acc[0][n2][2], acc[0][n2][3],
                         af[0][0], af[0][1], af[0][2], af[0][3], b0, b1);
                MMA_BF16(acc[1][n2][0], acc[1][n2][1], acc[1][n2][2], acc[1][n2][3],
                         af[1][0], af[1][1], af[1][2], af[1][3], b0, b1);
            }
        }
        __syncthreads();
        buf ^= 1;
    }

    #pragma unroll
    for (int mt = 0; mt < 2; mt++) {
        int row = row0 + wm*32 + mt*16 + gid;
        #pragma unroll
        for (int n2 = 0; n2 < 8; n2++) {
            int col = col0 + wn*64 + n2*8 + tid4*2;
            float2 v0 = make_float2(acc[mt][n2][0], acc[mt][n2][1]);
            float2 v1 = make_float2(acc[mt][n2][2], acc[mt][n2][3]);
            if (res) {
                float2 r0 = *(const float2*)&res[(size_t)row*N + col];
                float2 r1 = *(const float2*)&res[(size_t)(row+8)*N + col];
                v0.x += r0.x; v0.y += r0.y;
                v1.x += r1.x; v1.y += r1.y;
            }
            if (round_out) {
                v0.x = rnd(v0.x); v0.y = rnd(v0.y);
                v1.x = rnd(v1.x); v1.y = rnd(v1.y);
            }
            *(float2*)&C[(size_t)row*N + col]     = v0;
            *(float2*)&C[(size_t)(row+8)*N + col] = v1;
        }
    }
}

// ---------------- RoPE (in place, tf32-rounded output) -----------------------
__global__ void rope_kernel() {
    int i = blockIdx.x * blockDim.x + threadIdx.x;
    const int NPAIR = BB*KK*HEADS*32;
    if (i >= 2*NPAIR) return;
    int which = (i >= NPAIR);
    int r = which ? (i - NPAIR) : i;
    int d  = r & 31;
    int hh = (r >> 5) & 15;
    int j  = (r >> 9) & (KK-1);
    int b  = r >> (9 + 9);
    float* base = which ? g_k : g_q;
    int off = ((b*KK + j)*HEADS + hh)*HDIM;
    float inv = expf(-logf(10000.f) * (float)d / 32.f);
    float pos = (float)g_idx[b*KK + j];
    float ang = pos * inv;
    float c = cosf(ang), s = sinf(ang);
    float x1 = base[off + d];
    float x2 = base[off + d + 32];
    base[off + d]      = rnd(x1*c - x2*s);
    base[off + d + 32] = rnd(x2*c + x1*s);
}

// ---------------- tf32 flash attention, bf16 output --------------------------
__global__ __launch_bounds__(128) void attn_tc() {
    __shared__ float Qs[64][68];
    __shared__ float Ks[64][68];
    __shared__ float Vs[64][72];
    __shared__ float Ps[4][16][68];
    int qt = blockIdx.x, h = blockIdx.y, b = blockIdx.z;
    int tid = threadIdx.x, w = tid >> 5, lane = tid & 31;
    int gid = lane >> 2, tid4 = lane & 3;

    for (int f = tid; f < 64*16; f += 128) {
        int q = f >> 4, d4 = (f & 15) << 2;
        *(float4*)&Qs[q][d4] =
            *(const float4*)&g_q[((size_t)((b*KK + qt*64 + q)*HEADS + h))*HDIM + d4];
    }

    int r0g = qt*64 + w*16 + gid;
    int r1g = r0g + 8;

    float m0 = -1e30f, m1 = -1e30f, l0 = 0.f, l1 = 0.f;
    float oa[8][4];
    #pragma unroll
    for (int n2 = 0; n2 < 8; n2++)
        #pragma unroll
        for (int c = 0; c < 4; c++) oa[n2][c] = 0.f;

    for (int kt = 0; kt <= qt; kt++) {
        __syncthreads();
        for (int f = tid; f < 64*16; f += 128) {
            int k = f >> 4, d4 = (f & 15) << 2;
            size_t base = ((size_t)((b*KK + kt*64 + k)*HEADS + h))*HDIM + d4;
            *(float4*)&Ks[k][d4] = *(const float4*)&g_k[base];
            *(float4*)&Vs[k][d4] = *(const float4*)&g_v[base];
        }
        __syncthreads();

        float sc[8][4];
        #pragma unroll
        for (int n2 = 0; n2 < 8; n2++)
            #pragma unroll
            for (int c = 0; c < 4; c++) sc[n2][c] = 0.f;

        #pragma unroll
        for (int ks = 0; ks < 8; ks++) {
            int kb = ks * 8;
            uint32_t a0 = __float_as_uint(Qs[w*16 + gid    ][kb + tid4    ]);
            uint32_t a1 = __float_as_uint(Qs[w*16 + gid + 8][kb + tid4    ]);
            uint32_t a2 = __float_as_uint(Qs[w*16 + gid    ][kb + tid4 + 4]);
            uint32_t a3 = __float_as_uint(Qs[w*16 + gid + 8][kb + tid4 + 4]);
            #pragma unroll
            for (int n2 = 0; n2 < 8; n2++) {
                uint32_t b0 = __float_as_uint(Ks[n2*8 + gid][kb + tid4    ]);
                uint32_t b1 = __float_as_uint(Ks[n2*8 + gid][kb + tid4 + 4]);
                MMA_TF32(sc[n2][0], sc[n2][1], sc[n2][2], sc[n2][3],
                         a0, a1, a2, a3, b0, b1);
            }
        }

        bool diag = (kt == qt);
        float mx0 = -1e30f, mx1 = -1e30f;
        #pragma unroll
        for (int n2 = 0; n2 < 8; n2++) {
            int col = kt*64 + n2*8 + 2*tid4;
            sc[n2][0] *= 0.125f; sc[n2][1] *= 0.125f;
            sc[n2][2] *= 0.125f; sc[n2][3] *= 0.125f;
            if (diag) {
                if (col     > r0g) sc[n2][0] = -1e30f;
                if (col + 1 > r0g) sc[n2][1] = -1e30f;
                if (col     > r1g) sc[n2][2] = -1e30f;
                if (col + 1 > r1g) sc[n2][3] = -1e30f;
            }
            mx0 = fmaxf(mx0, fmaxf(sc[n2][0], sc[n2][1]));
            mx1 = fmaxf(mx1, fmaxf(sc[n2][2], sc[n2][3]));
        }
        #pragma unroll
        for (int o = 1; o <= 2; o <<= 1) {
            mx0 = fmaxf(mx0, __shfl_xor_sync(0xffffffffu, mx0, o));
            mx1 = fmaxf(mx1, __shfl_xor_sync(0xffffffffu, mx1, o));
        }
        float mn0 = fmaxf(m0, mx0), mn1 = fmaxf(m1, mx1);
        float cor0 = __expf(m0 - mn0), cor1 = __expf(m1 - mn1);
        m0 = mn0; m1 = mn1;
        float rs0 = 0.f, rs1 = 0.f;
        #pragma unroll
        for (int n2 = 0; n2 < 8; n2++) {
            float p0 = __expf(sc[n2][0] - mn0);
            float p1 = __expf(sc[n2][1] - mn0);
            float p2 = __expf(sc[n2][2] - mn1);
            float p3 = __expf(sc[n2][3] - mn1);
            rs0 += p0 + p1; rs1 += p2 + p3;
            *(float2*)&Ps[w][gid    ][n2*8 + 2*tid4] = make_float2(rnd(p0), rnd(p1));
            *(float2*)&Ps[w][gid + 8][n2*8 + 2*tid4] = make_float2(rnd(p2), rnd(p3));
        }
        #pragma unroll
        for (int o = 1; o <= 2; o <<= 1) {
            rs0 += __shfl_xor_sync(0xffffffffu, rs0, o);
            rs1 += __shfl_xor_sync(0xffffffffu, rs1, o);
        }
        l0 = l0 * cor0 + rs0;
        l1 = l1 * cor1 + rs1;
        #pragma unroll
        for (int n2 = 0; n2 < 8; n2++) {
            oa[n2][0] *= cor0; oa[n2][1] *= cor0;
            oa[n2][2] *= cor1; oa[n2][3] *= cor1;
        }
        __syncwarp();

        #pragma unroll
        for (int ks = 0; ks < 8; ks++) {
            uint32_t a0 = __float_as_uint(Ps[w][gid    ][ks*8 + tid4    ]);
            uint32_t a1 = __float_as_uint(Ps[w][gid + 8][ks*8 + tid4    ]);
            uint32_t a2 = __float_as_uint(Ps[w][gid    ][ks*8 + tid4 + 4]);
            uint32_t a3 = __float_as_uint(Ps[w][gid + 8][ks*8 + tid4 + 4]);
            #pragma unroll
            for (int n2 = 0; n2 < 8; n2++) {
                uint32_t b0 = __float_as_uint(Vs[ks*8 + tid4    ][n2*8 + gid]);
                uint32_t b1 = __float_as_uint(Vs[ks*8 + tid4 + 4][n2*8 + gid]);
                MMA_TF32(oa[n2][0], oa[n2][1], oa[n2][2], oa[n2][3],
                         a0, a1, a2, a3, b0, b1);
            }
        }
        __syncwarp();
    }

    float i0 = 1.f / l0, i1 = 1.f / l1;
    #pragma unroll
    for (int n2 = 0; n2 < 8; n2++) {
        int d = n2*8 + 2*tid4;
        uint32_t p0 = pack_bf2(oa[n2][0]*i0, oa[n2][1]*i0);
        uint32_t p1 = pack_bf2(oa[n2][2]*i1, oa[n2][3]*i1);
        *(uint32_t*)&g_ob[((size_t)((b*KK + r0g)*HEADS + h))*HDIM + d] = p0;
        *(uint32_t*)&g_ob[((size_t)((b*KK + r1g)*HEADS + h))*HDIM + d] = p1;
    }
}

// ---------------- silu(gate)*up -> bf16 --------------------------------------
__global__ void silu_mul_kernel() {
    int i = blockIdx.x * blockDim.x + threadIdx.x;
    const int N4 = BKr*FF/4;
    if (i >= N4) return;
    float4 g = ((const float4*)g_gateb)[i];
    float4 u = ((const float4*)g_upb)[i];
    float a = g.x / (1.f + __expf(-g.x)) * u.x;
    float b = g.y / (1.f + __expf(-g.y)) * u.y;
    float c = g.z / (1.f + __expf(-g.z)) * u.z;
    float d = g.w / (1.f + __expf(-g.w)) * u.w;
    *(uint2*)&g_mlpa[(size_t)i*4] = make_uint2(pack_bf2(a, b), pack_bf2(c, d));
}

// ---------------- final gated residual scatter --------------------------------
__global__ void scatter_kernel(float* __restrict__ out) {
    int bj = blockIdx.x;
    int b = bj >> 9;
    int row = g_idx[bj];
    float gate = g_gates[bj];
    float4 xs = ((const float4*)g_xsel)[bj*256 + threadIdx.x];
    float4 bo = ((const float4*)g_bo)[bj*256 + threadIdx.x];
    float4 o;
    o.x = xs.x + gate*(bo.x - xs.x);
    o.y = xs.y + gate*(bo.y - xs.y);
    o.z = xs.z + gate*(bo.z - xs.z);
    o.w = xs.w + gate*(bo.w - xs.w);
    ((float4*)out)[((size_t)(b*TT + row))*256 + threadIdx.x] = o;
}

// ---------------- launch -------------------------------------------------------
extern "C" void kernel_launch(void* const* d_in, const int* in_sizes, int n_in,
                              void* d_out, int out_size) {
    const float* hs  = (const float*)d_in[0];
    const float* wr  = (const float*)d_in[1];
    const float* wq  = (const float*)d_in[2];
    const float* wk  = (const float*)d_in[3];
    const float* wv  = (const float*)d_in[4];
    const float* wo  = (const float*)d_in[5];
    const float* ln1 = (const float*)d_in[6];
    const float* ln2 = (const float*)d_in[7];
    const float* wg  = (const float*)d_in[8];
    const float* wu  = (const float*)d_in[9];
    const float* wd  = (const float*)d_in[10];
    float* out = (float*)d_out;

    float *p_xsel, *p_q, *p_k, *p_v, *p_x1, *p_gate, *p_up, *p_bo;
    __nv_bfloat16 *p_hb, *p_ob, *p_h2b, *p_mlpa;
    uint32_t *p_wp;
    cudaGetSymbolAddress((void**)&p_xsel, g_xsel);
    cudaGetSymbolAddress((void**)&p_q,    g_q);
    cudaGetSymbolAddress((void**)&p_k,    g_k);
    cudaGetSymbolAddress((void**)&p_v,    g_v);
    cudaGetSymbolAddress((void**)&p_x1,   g_x1);
    cudaGetSymbolAddress((void**)&p_gate, g_gateb);
    cudaGetSymbolAddress((void**)&p_up,   g_upb);
    cudaGetSymbolAddress((void**)&p_bo,   g_bo);
    cudaGetSymbolAddress((void**)&p_hb,   g_hb);
    cudaGetSymbolAddress((void**)&p_ob,   g_ob);
    cudaGetSymbolAddress((void**)&p_h2b,  g_h2b);
    cudaGetSymbolAddress((void**)&p_mlpa, g_mlpa);
    cudaGetSymbolAddress((void**)&p_wp,   g_wpack);

    uint32_t* rwq = p_wp;                       // [DD/2][DD]
    uint32_t* rwk = p_wp + NW1/2;
    uint32_t* rwv = p_wp + 2*(NW1/2);
    uint32_t* rwo = p_wp + 3*(NW1/2);
    uint32_t* rwg = p_wp + 4*(NW1/2);           // [DD/2][FF]
    uint32_t* rwu = p_wp + 4*(NW1/2) + NWF/2;
    uint32_t* rwd = p_wp + 4*(NW1/2) + 2*(NWF/2);  // [FF/2][DD]

    cudaMemcpyAsync(out, hs, (size_t)BT*DD*sizeof(float), cudaMemcpyDeviceToDevice);

    // pack weights: fp32 [K][N] -> bf16-pair u32 [K/2][N]
    pack_kernel<<<(NW1/8 + 255)/256, 256>>>(wq, rwq, DD, NW1/8);
    pack_kernel<<<(NW1/8 + 255)/256, 256>>>(wk, rwk, DD, NW1/8);
    pack_kernel<<<(NW1/8 + 255)/256, 256>>>(wv, rwv, DD, NW1/8);
    pack_kernel<<<(NW1/8 + 255)/256, 256>>>(wo, rwo, DD, NW1/8);
    pack_kernel<<<(NWF/8 + 255)/256, 256>>>(wg, rwg, FF, NWF/8);
    pack_kernel<<<(NWF/8 + 255)/256, 256>>>(wu, rwu, FF, NWF/8);
    pack_kernel<<<(NWF/8 + 255)/256, 256>>>(wd, rwd, DD, NWF/8);

    router_kernel<<<BT/8, 256>>>(hs, wr);
    topk_kernel<<<BB, 1024>>>();
    aux_kernel<<<1, 1024>>>(out, out_size - 1);
    gather_rms1<<<BKr, 256>>>(hs, ln1);

    // fused QKV, outputs tf32-rounded fp32 for attention
    gemm_bf<<<dim3(DD/128, BKr/128, 3), 256>>>(p_hb, rwq, rwk, rwv, nullptr,
                                               p_q, p_k, p_v, BKr, DD, DD, 1);

    rope_kernel<<<(2*BB*KK*HEADS*32 + 255)/256, 256>>>();

    attn_tc<<<dim3(KK/64, HEADS, BB), 128>>>();

    gemm_bf<<<dim3(DD/128, BKr/128, 1), 256>>>(p_ob, rwo, rwo, rwo, p_xsel,
                                               p_x1, p_x1, p_x1, BKr, DD, DD, 0);
    rms2_kernel<<<BKr, 256>>>(ln2);

    gemm_bf<<<dim3(FF/128, BKr/128, 2), 256>>>(p_h2b, rwg, rwu, rwu, nullptr,
                                               p_gate, p_up, p_up, BKr, FF, DD, 0);
    silu_mul_kernel<<<(BKr*FF/4 + 255)/256, 256>>>();
    gemm_bf<<<dim3(DD/128, BKr/128, 1), 256>>>(p_mlpa, rwd, rwd, rwd, p_x1,
                                               p_bo, p_bo, p_bo, BKr, DD, FF, 0);

    scatter_kernel<<<BKr, 256>>>(out);
}